// round 14
// baseline (speedup 1.0000x reference)
#include <cuda_runtime.h>
#include <cuda_bf16.h>
#include <cuda_fp16.h>
#include <cstdint>

#define H     256
#define SEQL  10
#define BQ    2048
#define NTOT  327680
#define NSEG  (BQ * SEQL)  // 20480
#define NENT  20000

// ---------------- scratch (no cudaMalloc allowed) ----------------
__device__ __half g_EW1h[NENT * H];    // ent_embeds @ W1 in fp16 (10 MB)
__device__ __half g_ENTh[NENT * H];    // ent_embeds in fp16 (10 MB, gather)
__device__ __nv_bfloat16 g_Ehi[NENT * H];  // ent hi (bf16) for MMA
__device__ __nv_bfloat16 g_Elo[NENT * H];  // ent lo residual
__device__ float g_A[BQ * H];          // s@W2 + r@W3 + b   (2 MB)
__device__ float g_scores[NTOT];       // spill store for huge queries (rare)
__device__ int   g_starts[NSEG + 1];   // segment start offsets
__device__ __nv_bfloat16 g_Wt_hi[H * H];  // W1^T hi (bf16), [n][k]
__device__ __nv_bfloat16 g_Wt_lo[H * H];  // W1^T lo residual

// Packed fp32x2 FMA (Blackwell): two fp32 FMAs per instruction.
__device__ __forceinline__ float2 ffma2(float2 a, float2 b, float2 c) {
    float2 d;
    asm("fma.rn.f32x2 %0, %1, %2, %3;"
        : "=l"(reinterpret_cast<unsigned long long&>(d))
        : "l"(reinterpret_cast<const unsigned long long&>(a)),
          "l"(reinterpret_cast<const unsigned long long&>(b)),
          "l"(reinterpret_cast<const unsigned long long&>(c)));
    return d;
}

__device__ __forceinline__ float tanh_fast(float x) {
    float y;
    asm("tanh.approx.f32 %0, %1;" : "=f"(y) : "f"(x));
    return y;
}

__device__ __forceinline__ float2 f2lo(float4 v) { return make_float2(v.x, v.y); }
__device__ __forceinline__ float2 f2hi(float4 v) { return make_float2(v.z, v.w); }

__device__ __forceinline__ uint32_t smem_u32(const void* p) {
    uint32_t a;
    asm("{ .reg .u64 t; cvta.to.shared.u64 t, %1; cvt.u32.u64 %0, t; }"
        : "=r"(a) : "l"(p));
    return a;
}

__device__ __forceinline__ uint32_t sw128(uint32_t x) {
    return x ^ ((x >> 3) & 0x70);
}

__device__ __forceinline__ void ldsm_x4(uint32_t* r, uint32_t addr) {
    asm volatile("ldmatrix.sync.aligned.m8n8.x4.shared.b16 {%0,%1,%2,%3}, [%4];"
                 : "=r"(r[0]), "=r"(r[1]), "=r"(r[2]), "=r"(r[3]) : "r"(addr));
}

__device__ __forceinline__ void mma_bf16(float* c, const uint32_t* a,
                                         const uint32_t* b) {
    asm volatile(
        "mma.sync.aligned.m16n8k16.row.col.f32.bf16.bf16.f32 "
        "{%0,%1,%2,%3}, {%4,%5,%6,%7}, {%8,%9}, {%0,%1,%2,%3};"
        : "+f"(c[0]), "+f"(c[1]), "+f"(c[2]), "+f"(c[3])
        : "r"(a[0]), "r"(a[1]), "r"(a[2]), "r"(a[3]), "r"(b[0]), "r"(b[1]));
}

// ===========================================================================
// Kernel 0 (FUSED prep):
//  blocks [0, 64):         transpose+split W1 into g_Wt_hi/lo
//  blocks [64, 1344):      segment start offsets from sorted seg_ids
//  blocks [1344, 6344):    split ent into g_Ehi/g_Elo (bf16) + g_ENTh (fp16)
// ===========================================================================
#define PREP_W 64
#define PREP_ST (PREP_W + (NTOT + 255) / 256)               // 1344
#define PREP_TOT (PREP_ST + (NENT * H / 4 + 255) / 256)     // 6344

__global__ void __launch_bounds__(256)
prep_kernel(const int* __restrict__ seg_ids, const float* __restrict__ W,
            const float* __restrict__ ent) {
    const int bid = blockIdx.x;
    if (bid < PREP_W) {
        __shared__ float t[32][33];
        const int bx = bid & 7;
        const int by = bid >> 3;
        const int tx = threadIdx.x & 31;
        const int ty = threadIdx.x >> 5;
#pragma unroll
        for (int i = 0; i < 4; i++) {
            const int k = bx * 32 + ty + i * 8;
            const int n = by * 32 + tx;
            t[ty + i * 8][tx] = W[k * H + n];
        }
        __syncthreads();
#pragma unroll
        for (int i = 0; i < 4; i++) {
            const int n = by * 32 + ty + i * 8;
            const int k = bx * 32 + tx;
            const float x = t[tx][ty + i * 8];
            const __nv_bfloat16 hi = __float2bfloat16(x);
            const __nv_bfloat16 lo = __float2bfloat16(x - __bfloat162float(hi));
            g_Wt_hi[n * H + k] = hi;
            g_Wt_lo[n * H + k] = lo;
        }
    } else if (bid < PREP_ST) {
        const int i = (bid - PREP_W) * 256 + threadIdx.x;
        if (i >= NTOT) return;
        const int cur  = seg_ids[i];
        const int prev = (i == 0) ? -1 : seg_ids[i - 1];
        for (int sg = prev + 1; sg <= cur; sg++) g_starts[sg] = i;
        if (i == NTOT - 1)
            for (int sg = cur + 1; sg <= NSEG; sg++) g_starts[sg] = NTOT;
    } else {
        const int i = (bid - PREP_ST) * 256 + threadIdx.x;  // float4 index
        if (i >= NENT * H / 4) return;
        const float4 x = reinterpret_cast<const float4*>(ent)[i];
        // fp16 copy (for pass-2 gather)
        __half2* eh = reinterpret_cast<__half2*>(g_ENTh) + 2 * (size_t)i;
        eh[0] = __floats2half2_rn(x.x, x.y);
        eh[1] = __floats2half2_rn(x.z, x.w);
        // bf16 hi/lo split (for MMA)
        const __nv_bfloat16 h0 = __float2bfloat16(x.x);
        const __nv_bfloat16 h1 = __float2bfloat16(x.y);
        const __nv_bfloat16 h2 = __float2bfloat16(x.z);
        const __nv_bfloat16 h3 = __float2bfloat16(x.w);
        __nv_bfloat162* ph = reinterpret_cast<__nv_bfloat162*>(g_Ehi) + 2 * (size_t)i;
        __nv_bfloat162* pl = reinterpret_cast<__nv_bfloat162*>(g_Elo) + 2 * (size_t)i;
        ph[0] = __halves2bfloat162(h0, h1);
        ph[1] = __halves2bfloat162(h2, h3);
        pl[0] = __halves2bfloat162(
                    __float2bfloat16(x.x - __bfloat162float(h0)),
                    __float2bfloat16(x.y - __bfloat162float(h1)));
        pl[1] = __halves2bfloat162(
                    __float2bfloat16(x.z - __bfloat162float(h2)),
                    __float2bfloat16(x.w - __bfloat162float(h3)));
    }
}

// ===========================================================================
// Kernel 1 (MERGED GEMMs, one launch, 884 blocks):
//  blocks [0, 256):    aq path  — A = [s|r] @ W[256:768] + b, 32x64 FFMA2 tiles
//  blocks [256, 884):  ew1 path — EW1 = ent @ W1 via HMMA bf16 hi/lo
//                      (pre-split operands -> staging is pure uint4 copies);
//                      epilogue stores fp16.
// ===========================================================================
#define AQ_BLOCKS  256              // 64 qBase x 4 nBase
#define EW1_BLOCKS 628              // 157 eBase x 4 nBase
#define MM_AHI 0
#define MM_ALO 16384
#define MM_BHI 32768
#define MM_BLO 40960
#define MM_SMEM 49152

// ---- aq sub-kernel: QBM=32, QBN=64, BK=32, FFMA2, register prefetch ----
__device__ __forceinline__ void aq_path(char* smem, int bid,
                                        const int* __restrict__ s,
                                        const int* __restrict__ r,
                                        const float* __restrict__ ent,
                                        const float* __restrict__ rel,
                                        const float* __restrict__ W,
                                        const float* __restrict__ b) {
    float4* sA = reinterpret_cast<float4*>(smem);            // 32*17 = 544 f4
    float4* sW = reinterpret_cast<float4*>(smem + 8704);     // 512 f4
    int* sidx  = reinterpret_cast<int*>(smem + 8704 + 8192); // 32
    int* ridx  = sidx + 32;

    const int tid   = threadIdx.x;
    const int tm    = tid >> 4;            // 0..15 (2 rows each)
    const int tn    = tid & 15;            // 0..15 (4 cols)
    const int qBase = (bid & 63) * 32;
    const int nBase = (bid >> 6) * 64;

    if (tid < 32) { sidx[tid] = s[qBase + tid]; ridx[tid] = r[qBase + tid]; }
    __syncthreads();

    const int e0  = tid >> 3;              // 0..31 A row
    const int k4  = tid & 7;               // A f4-in-row
    const int swk = tid >> 4;              // W rows swk, swk+16
    const int swc = tid & 15;

    float2 acc[2][2];
#pragma unroll
    for (int e = 0; e < 2; e++) {
        acc[e][0] = make_float2(0.f, 0.f);
        acc[e][1] = make_float2(0.f, 0.f);
    }

    auto aSrc = [&](int kc, int e) -> const float* {
        return (kc < H) ? ent + (size_t)sidx[e] * H + kc
                        : rel + (size_t)ridx[e] * H + (kc - H);
    };

    float4 pa  = *reinterpret_cast<const float4*>(aSrc(0, e0) + k4 * 4);
    float4 pw0 = *(reinterpret_cast<const float4*>(
                       W + (size_t)(H + swk) * H + nBase) + swc);
    float4 pw1 = *(reinterpret_cast<const float4*>(
                       W + (size_t)(H + swk + 16) * H + nBase) + swc);

#pragma unroll 1
    for (int kc = 0; kc < 2 * H; kc += 32) {
        if (kc) __syncthreads();
        sA[e0 * 17 + k4 * 2 + 0] = make_float4(pa.x, pa.x, pa.y, pa.y);
        sA[e0 * 17 + k4 * 2 + 1] = make_float4(pa.z, pa.z, pa.w, pa.w);
        sW[swk * 16 + swc]        = pw0;
        sW[(swk + 16) * 16 + swc] = pw1;
        __syncthreads();

        if (kc + 32 < 2 * H) {
            const int kn = kc + 32;
            pa  = *reinterpret_cast<const float4*>(aSrc(kn, e0) + k4 * 4);
            pw0 = *(reinterpret_cast<const float4*>(
                        W + (size_t)(H + kn + swk) * H + nBase) + swc);
            pw1 = *(reinterpret_cast<const float4*>(
                        W + (size_t)(H + kn + swk + 16) * H + nBase) + swc);
        }

#pragma unroll
        for (int k2 = 0; k2 < 16; k2++) {
            const float4 w0 = sW[(2 * k2) * 16 + tn];
            const float4 w1 = sW[(2 * k2 + 1) * 16 + tn];
#pragma unroll
            for (int e = 0; e < 2; e++) {
                const float4 a = sA[(tm * 2 + e) * 17 + k2];
                acc[e][0] = ffma2(f2lo(a), f2lo(w0), acc[e][0]);
                acc[e][1] = ffma2(f2lo(a), f2hi(w0), acc[e][1]);
                acc[e][0] = ffma2(f2hi(a), f2lo(w1), acc[e][0]);
                acc[e][1] = ffma2(f2hi(a), f2hi(w1), acc[e][1]);
            }
        }
    }

    const float4 b4 = *reinterpret_cast<const float4*>(b + nBase + tn * 4);
#pragma unroll
    for (int e = 0; e < 2; e++) {
        float* row = g_A + (size_t)(qBase + tm * 2 + e) * H + nBase;
        *reinterpret_cast<float4*>(row + tn * 4) =
            make_float4(acc[e][0].x + b4.x, acc[e][0].y + b4.y,
                        acc[e][1].x + b4.z, acc[e][1].y + b4.w);
    }
}

// ---- ew1 sub-kernel: HMMA bf16 hi/lo from pre-split operands ----
__device__ __forceinline__ void ew1_path(char* smem, int bid) {
    const uint32_t sb = smem_u32(smem);
    const int tid   = threadIdx.x;
    const int wid   = tid >> 5;
    const int lane  = tid & 31;
    const int wm    = wid & 3;
    const int wn    = wid >> 2;
    const int eBase = (bid % 157) * 128;
    const int nBase = (bid / 157) * 64;

    const int lmat = lane >> 3;
    const int lrow = lane & 7;

    float acc[2][4][4];
#pragma unroll
    for (int mt = 0; mt < 2; mt++)
#pragma unroll
        for (int nt = 0; nt < 4; nt++)
#pragma unroll
            for (int j = 0; j < 4; j++) acc[mt][nt][j] = 0.0f;

#pragma unroll 1
    for (int c = 0; c < 4; c++) {
        const int kc = c * 64;
        if (c) __syncthreads();

        // ---- stage A hi/lo: 128 rows x 64 bf16 = 1024 uint4 -> 4/thread ----
#pragma unroll
        for (int it = 0; it < 4; it++) {
            const int idx = tid + it * 256;        // 0..1023
            const int row = idx >> 3;
            const int seg = idx & 7;
            int er = eBase + row; if (er >= NENT) er = 0;
            const uint4 vh = *reinterpret_cast<const uint4*>(
                                 g_Ehi + (size_t)er * H + kc + seg * 8);
            const uint4 vl = *reinterpret_cast<const uint4*>(
                                 g_Elo + (size_t)er * H + kc + seg * 8);
            const uint32_t sw = sw128(row * 128 + seg * 16);
            *reinterpret_cast<uint4*>(smem + MM_AHI + sw) = vh;
            *reinterpret_cast<uint4*>(smem + MM_ALO + sw) = vl;
        }
        // ---- stage B hi/lo: 64 n-rows x 64 bf16 = 512 uint4 -> 2/thread ----
#pragma unroll
        for (int it = 0; it < 2; it++) {
            const int idx = tid + it * 256;        // 0..511
            const int n   = idx >> 3;
            const int seg = idx & 7;
            const uint4 vh = *reinterpret_cast<const uint4*>(
                                 g_Wt_hi + (nBase + n) * H + kc + seg * 8);
            const uint4 vl = *reinterpret_cast<const uint4*>(
                                 g_Wt_lo + (nBase + n) * H + kc + seg * 8);
            const uint32_t sw = sw128(n * 128 + seg * 16);
            *reinterpret_cast<uint4*>(smem + MM_BHI + sw) = vh;
            *reinterpret_cast<uint4*>(smem + MM_BLO + sw) = vl;
        }
        __syncthreads();

#pragma unroll
        for (int kk = 0; kk < 4; kk++) {
            uint32_t ah[2][4], al[2][4];
#pragma unroll
            for (int mt = 0; mt < 2; mt++) {
                const int arow = wm * 32 + mt * 16 + ((lmat & 1) << 3) + lrow;
                const int akb  = (kk * 16 + ((lmat >> 1) << 3)) * 2;
                const uint32_t off = sw128(arow * 128 + akb);
                ldsm_x4(ah[mt], sb + MM_AHI + off);
                ldsm_x4(al[mt], sb + MM_ALO + off);
            }
            uint32_t bh[4][2], bl[4][2];
#pragma unroll
            for (int np = 0; np < 2; np++) {
                const int brow = wn * 32 + np * 16 + ((lmat >> 1) << 3) + lrow;
                const int bkb  = (kk * 16 + ((lmat & 1) << 3)) * 2;
                const uint32_t off = sw128(brow * 128 + bkb);
                uint32_t th[4], tl[4];
                ldsm_x4(th, sb + MM_BHI + off);
                ldsm_x4(tl, sb + MM_BLO + off);
                bh[2 * np + 0][0] = th[0]; bh[2 * np + 0][1] = th[1];
                bh[2 * np + 1][0] = th[2]; bh[2 * np + 1][1] = th[3];
                bl[2 * np + 0][0] = tl[0]; bl[2 * np + 0][1] = tl[1];
                bl[2 * np + 1][0] = tl[2]; bl[2 * np + 1][1] = tl[3];
            }
#pragma unroll
            for (int mt = 0; mt < 2; mt++)
#pragma unroll
                for (int nt = 0; nt < 4; nt++) {
                    mma_bf16(acc[mt][nt], ah[mt], bh[nt]);
                    mma_bf16(acc[mt][nt], ah[mt], bl[nt]);
                    mma_bf16(acc[mt][nt], al[mt], bh[nt]);
                }
        }
    }

    // epilogue: fp32 acc -> fp16 EW1
    const int gr = lane >> 2;
    const int gc = (lane & 3) * 2;
#pragma unroll
    for (int mt = 0; mt < 2; mt++) {
        const int m0 = eBase + wm * 32 + mt * 16 + gr;
        const int m1 = m0 + 8;
#pragma unroll
        for (int nt = 0; nt < 4; nt++) {
            const int n = nBase + wn * 32 + nt * 8 + gc;
            if (m0 < NENT)
                *reinterpret_cast<__half2*>(g_EW1h + (size_t)m0 * H + n) =
                    __floats2half2_rn(acc[mt][nt][0], acc[mt][nt][1]);
            if (m1 < NENT)
                *reinterpret_cast<__half2*>(g_EW1h + (size_t)m1 * H + n) =
                    __floats2half2_rn(acc[mt][nt][2], acc[mt][nt][3]);
        }
    }
}

__global__ void __launch_bounds__(256)
gemm_kernel(const float* __restrict__ ent,
            const int* __restrict__ s, const int* __restrict__ r,
            const float* __restrict__ rel,
            const float* __restrict__ W, const float* __restrict__ b) {
    extern __shared__ char smem[];
    const int bid = blockIdx.x;
    if (bid < AQ_BLOCKS) aq_path(smem, bid, s, r, ent, rel, W, b);
    else                 ew1_path(smem, bid - AQ_BLOCKS);
}

// ---------------------------------------------------------------------------
// Kernel 2 (FUSED, QUERY-PER-BLOCK): pass 1 reads fp16 EW1; pass 2 gathers
// fp16 ent rows (half the traffic), float4 output grain, 4 segment groups.
// ---------------------------------------------------------------------------
#define QCAP 512
__global__ void __launch_bounds__(256)
scoreagg_kernel(const int* __restrict__ s, const int* __restrict__ r,
                const int* __restrict__ nbr_ids,
                const float* __restrict__ ent,
                const float* __restrict__ rel,
                const float* __restrict__ v,
                float* __restrict__ out) {
    const int q    = blockIdx.x;
    const int tid  = threadIdx.x;
    const int w    = tid >> 5;
    const int lane = tid & 31;

    __shared__ int    sbnd[SEQL + 1];
    __shared__ float  wsm[QCAP];
    __shared__ int    nsm[QCAP];
    __shared__ float  sdsum[SEQL];

    if (tid <= SEQL) sbnd[tid] = g_starts[q * SEQL + tid];
    __syncthreads();
    const int qlo  = sbnd[0];
    const int qhi  = sbnd[SEQL];
    const int qcnt = qhi - qlo;

    // ---- pass 1: scores (2 neighbors per warp-iteration) ----
    if (qcnt > 0) {
        const float4* aq = reinterpret_cast<const float4*>(g_A + (size_t)q * H);
        const float4* vv = reinterpret_cast<const float4*>(v);
        const float4 a0 = aq[2 * lane], a1 = aq[2 * lane + 1];
        const float4 v0 = vv[2 * lane], v1 = vv[2 * lane + 1];

        for (int j0 = qlo + w; j0 < qhi; j0 += 16) {
            const int j1   = j0 + 8;
            const bool h1  = (j1 < qhi);
            const int n0   = nbr_ids[j0];
            const int n1   = nbr_ids[h1 ? j1 : j0];

            const uint4 eu0 = *reinterpret_cast<const uint4*>(
                                  g_EW1h + (size_t)n0 * H + lane * 8);
            const uint4 eu1 = *reinterpret_cast<const uint4*>(
                                  g_EW1h + (size_t)n1 * H + lane * 8);
            const __half2* e0 = reinterpret_cast<const __half2*>(&eu0);
            const __half2* e1 = reinterpret_cast<const __half2*>(&eu1);
            const float2 p0 = __half22float2(e0[0]);
            const float2 p1 = __half22float2(e0[1]);
            const float2 p2 = __half22float2(e0[2]);
            const float2 p3 = __half22float2(e0[3]);
            const float2 r0 = __half22float2(e1[0]);
            const float2 r1 = __half22float2(e1[1]);
            const float2 r2 = __half22float2(e1[2]);
            const float2 r3 = __half22float2(e1[3]);

            float sc0, sc1;
            sc0 = tanh_fast(p0.x + a0.x) * v0.x;
            sc1 = tanh_fast(r0.x + a0.x) * v0.x;
            sc0 = fmaf(tanh_fast(p0.y + a0.y), v0.y, sc0);
            sc1 = fmaf(tanh_fast(r0.y + a0.y), v0.y, sc1);
            sc0 = fmaf(tanh_fast(p1.x + a0.z), v0.z, sc0);
            sc1 = fmaf(tanh_fast(r1.x + a0.z), v0.z, sc1);
            sc0 = fmaf(tanh_fast(p1.y + a0.w), v0.w, sc0);
            sc1 = fmaf(tanh_fast(r1.y + a0.w), v0.w, sc1);
            sc0 = fmaf(tanh_fast(p2.x + a1.x), v1.x, sc0);
            sc1 = fmaf(tanh_fast(r2.x + a1.x), v1.x, sc1);
            sc0 = fmaf(tanh_fast(p2.y + a1.y), v1.y, sc0);
            sc1 = fmaf(tanh_fast(r2.y + a1.y), v1.y, sc1);
            sc0 = fmaf(tanh_fast(p3.x + a1.z), v1.z, sc0);
            sc1 = fmaf(tanh_fast(r3.x + a1.z), v1.z, sc1);
            sc0 = fmaf(tanh_fast(p3.y + a1.w), v1.w, sc0);
            sc1 = fmaf(tanh_fast(r3.y + a1.w), v1.w, sc1);
#pragma unroll
            for (int o = 16; o; o >>= 1) {
                sc0 += __shfl_xor_sync(0xffffffffu, sc0, o);
                sc1 += __shfl_xor_sync(0xffffffffu, sc1, o);
            }
            if (lane == 0) {
                const float e0v = __expf(sc0);
                const int k0 = j0 - qlo;
                if (k0 < QCAP) { wsm[k0] = e0v; nsm[k0] = n0; }
                else           g_scores[j0] = e0v;
                if (h1) {
                    const float e1v = __expf(sc1);
                    const int k1 = j1 - qlo;
                    if (k1 < QCAP) { wsm[k1] = e1v; nsm[k1] = n1; }
                    else           g_scores[j1] = e1v;
                }
            }
        }
    }
    __syncthreads();

    // ---- per-segment exp sums ----
    for (int t = w; t < SEQL; t += 8) {
        const int slo = sbnd[t]     - qlo;
        const int shi = sbnd[t + 1] - qlo;
        float d = 0.0f;
        for (int k = slo + lane; k < shi; k += 32)
            d += (k < QCAP) ? wsm[k] : g_scores[qlo + k];
#pragma unroll
        for (int o = 16; o; o >>= 1) d += __shfl_xor_sync(0xffffffffu, d, o);
        if (lane == 0) sdsum[t] = d;
    }

    // ---- pass 2: fp16 gather, float4 grain; group g owns {g, g+4, ...} ----
    const int g  = tid >> 6;               // 0..3
    const int h4 = tid & 63;               // float4 index within row
    const float4 s4 = *(reinterpret_cast<const float4*>(
                            ent + (size_t)s[q] * H) + h4);
    const float4 r4 = *(reinterpret_cast<const float4*>(
                            rel + (size_t)r[q] * H) + h4);
    __syncthreads();                        // wsm/nsm/sdsum ready

    float* qout = out + (size_t)q * SEQL * (3 * H);
#pragma unroll 1
    for (int t = g; t < SEQL; t += 4) {
        float* row = qout + (size_t)t * (3 * H);
        float4* rowA = reinterpret_cast<float4*>(row);
        float4* rowS = reinterpret_cast<float4*>(row + H);
        float4* rowR = reinterpret_cast<float4*>(row + 2 * H);
        const int slo = sbnd[t]     - qlo;
        const int shi = sbnd[t + 1] - qlo;

        if (slo >= shi) {
            const float4 z = make_float4(0.f, 0.f, 0.f, 0.f);
            rowA[h4] = z; rowS[h4] = z; rowR[h4] = z;
            continue;
        }
        const float inv = 1.0f / sdsum[t];
        const int c = min(shi, QCAP);

        float4 a0 = make_float4(0.f, 0.f, 0.f, 0.f);
        float4 a1 = make_float4(0.f, 0.f, 0.f, 0.f);
        int k = slo;
        for (; k + 1 < c; k += 2) {
            const float w0 = wsm[k], w1 = wsm[k + 1];
            const uint2 u0 = *reinterpret_cast<const uint2*>(
                                 g_ENTh + (size_t)nsm[k] * H + h4 * 4);
            const uint2 u1 = *reinterpret_cast<const uint2*>(
                                 g_ENTh + (size_t)nsm[k + 1] * H + h4 * 4);
            const __half2* q0 = reinterpret_cast<const __half2*>(&u0);
            const __half2* q1 = reinterpret_cast<const __half2*>(&u1);
            const float2 e0a = __half22float2(q0[0]);
            const float2 e0b = __half22float2(q0[1]);
            const float2 e1a = __half22float2(q1[0]);
            const float2 e1b = __half22float2(q1[1]);
            a0.x = fmaf(w0, e0a.x, a0.x); a0.y = fmaf(w0, e0a.y, a0.y);
            a0.z = fmaf(w0, e0b.x, a0.z); a0.w = fmaf(w0, e0b.y, a0.w);
            a1.x = fmaf(w1, e1a.x, a1.x); a1.y = fmaf(w1, e1a.y, a1.y);
            a1.z = fmaf(w1, e1b.x, a1.z); a1.w = fmaf(w1, e1b.y, a1.w);
        }
        for (; k < c; k++) {
            const float w0 = wsm[k];
            const uint2 u0 = *reinterpret_cast<const uint2*>(
                                 g_ENTh + (size_t)nsm[k] * H + h4 * 4);
            const __half2* q0 = reinterpret_cast<const __half2*>(&u0);
            const float2 e0a = __half22float2(q0[0]);
            const float2 e0b = __half22float2(q0[1]);
            a0.x = fmaf(w0, e0a.x, a0.x); a0.y = fmaf(w0, e0a.y, a0.y);
            a0.z = fmaf(w0, e0b.x, a0.z); a0.w = fmaf(w0, e0b.y, a0.w);
        }
        for (; k < shi; k++) {              // spill path (rare)
            const float w0 = g_scores[qlo + k];
            const uint2 u0 = *reinterpret_cast<const uint2*>(
                                 g_ENTh + (size_t)nbr_ids[qlo + k] * H + h4 * 4);
            const __half2* q0 = reinterpret_cast<const __half2*>(&u0);
            const float2 e0a = __half22float2(q0[0]);
            const float2 e0b = __half22float2(q0[1]);
            a0.x = fmaf(w0, e0a.x, a0.x); a0.y = fmaf(w0, e0a.y, a0.y);
            a0.z = fmaf(w0, e0b.x, a0.z); a0.w = fmaf(w0, e0b.y, a0.w);
        }

        rowA[h4] = make_float4((a0.x + a1.x) * inv, (a0.y + a1.y) * inv,
                               (a0.z + a1.z) * inv, (a0.w + a1.w) * inv);
        rowS[h4] = s4;
        rowR[h4] = r4;
    }
}

// ---------------------------------------------------------------------------
extern "C" void kernel_launch(void* const* d_in, const int* in_sizes, int n_in,
                              void* d_out, int out_size) {
    const int*   s    = (const int*)d_in[0];
    const int*   r    = (const int*)d_in[1];
    const int*   nbr  = (const int*)d_in[2];
    const int*   segi = (const int*)d_in[3];
    const float* ent  = (const float*)d_in[4];
    const float* rel  = (const float*)d_in[5];
    const float* W    = (const float*)d_in[6];
    const float* b    = (const float*)d_in[7];
    const float* v    = (const float*)d_in[8];
    float* out = (float*)d_out;

    cudaFuncSetAttribute(gemm_kernel,
                         cudaFuncAttributeMaxDynamicSharedMemorySize, MM_SMEM);

    prep_kernel<<<PREP_TOT, 256>>>(segi, W, ent);
    gemm_kernel<<<AQ_BLOCKS + EW1_BLOCKS, 256, MM_SMEM>>>(ent, s, r, rel, W, b);
    scoreagg_kernel<<<BQ, 256>>>(s, r, nbr, ent, rel, v, out);
}

// round 15
// speedup vs baseline: 1.0447x; 1.0447x over previous
#include <cuda_runtime.h>
#include <cuda_fp16.h>
#include <cstdint>

#define H     256
#define SEQL  10
#define BQ    2048
#define NTOT  327680
#define NSEG  (BQ * SEQL)  // 20480
#define NENT  20000

// ---------------- scratch (no cudaMalloc allowed) ----------------
__device__ __half g_EW1h[NENT * H];    // ent_embeds @ W1 in fp16 (10 MB)
__device__ __half g_Ehi[NENT * H];     // ent hi (fp16) for MMA
__device__ __half g_Elo[NENT * H];     // ent lo residual (fp16)
__device__ __half g_Wth[H * H];        // W1^T in fp16, [n][k]
__device__ float g_A[BQ * H];          // s@W2 + r@W3 + b   (2 MB)
__device__ float g_scores[NTOT];       // spill store for huge queries (rare)
__device__ int   g_starts[NSEG + 1];   // segment start offsets

// Packed fp32x2 FMA (Blackwell): two fp32 FMAs per instruction.
__device__ __forceinline__ float2 ffma2(float2 a, float2 b, float2 c) {
    float2 d;
    asm("fma.rn.f32x2 %0, %1, %2, %3;"
        : "=l"(reinterpret_cast<unsigned long long&>(d))
        : "l"(reinterpret_cast<const unsigned long long&>(a)),
          "l"(reinterpret_cast<const unsigned long long&>(b)),
          "l"(reinterpret_cast<const unsigned long long&>(c)));
    return d;
}

__device__ __forceinline__ float tanh_fast(float x) {
    float y;
    asm("tanh.approx.f32 %0, %1;" : "=f"(y) : "f"(x));
    return y;
}

__device__ __forceinline__ float2 f2lo(float4 v) { return make_float2(v.x, v.y); }
__device__ __forceinline__ float2 f2hi(float4 v) { return make_float2(v.z, v.w); }

__device__ __forceinline__ uint32_t smem_u32(const void* p) {
    uint32_t a;
    asm("{ .reg .u64 t; cvta.to.shared.u64 t, %1; cvt.u32.u64 %0, t; }"
        : "=r"(a) : "l"(p));
    return a;
}

__device__ __forceinline__ uint32_t sw128(uint32_t x) {
    return x ^ ((x >> 3) & 0x70);
}

__device__ __forceinline__ void ldsm_x4(uint32_t* r, uint32_t addr) {
    asm volatile("ldmatrix.sync.aligned.m8n8.x4.shared.b16 {%0,%1,%2,%3}, [%4];"
                 : "=r"(r[0]), "=r"(r[1]), "=r"(r[2]), "=r"(r[3]) : "r"(addr));
}

__device__ __forceinline__ void mma_f16(float* c, const uint32_t* a,
                                        const uint32_t* b) {
    asm volatile(
        "mma.sync.aligned.m16n8k16.row.col.f32.f16.f16.f32 "
        "{%0,%1,%2,%3}, {%4,%5,%6,%7}, {%8,%9}, {%0,%1,%2,%3};"
        : "+f"(c[0]), "+f"(c[1]), "+f"(c[2]), "+f"(c[3])
        : "r"(a[0]), "r"(a[1]), "r"(a[2]), "r"(a[3]), "r"(b[0]), "r"(b[1]));
}

// ===========================================================================
// Kernel 0 (FUSED prep):
//  blocks [0, 64):         transpose W1 -> g_Wth (fp16)
//  blocks [64, 1344):      segment start offsets from sorted seg_ids
//  blocks [1344, 6344):    split ent into g_Ehi/g_Elo (fp16 hi + residual)
// ===========================================================================
#define PREP_W 64
#define PREP_ST (PREP_W + (NTOT + 255) / 256)               // 1344
#define PREP_TOT (PREP_ST + (NENT * H / 4 + 255) / 256)     // 6344

__global__ void __launch_bounds__(256)
prep_kernel(const int* __restrict__ seg_ids, const float* __restrict__ W,
            const float* __restrict__ ent) {
    const int bid = blockIdx.x;
    if (bid < PREP_W) {
        __shared__ float t[32][33];
        const int bx = bid & 7;
        const int by = bid >> 3;
        const int tx = threadIdx.x & 31;
        const int ty = threadIdx.x >> 5;
#pragma unroll
        for (int i = 0; i < 4; i++) {
            const int k = bx * 32 + ty + i * 8;
            const int n = by * 32 + tx;
            t[ty + i * 8][tx] = W[k * H + n];
        }
        __syncthreads();
#pragma unroll
        for (int i = 0; i < 4; i++) {
            const int n = by * 32 + ty + i * 8;
            const int k = bx * 32 + tx;
            g_Wth[n * H + k] = __float2half_rn(t[tx][ty + i * 8]);
        }
    } else if (bid < PREP_ST) {
        const int i = (bid - PREP_W) * 256 + threadIdx.x;
        if (i >= NTOT) return;
        const int cur  = seg_ids[i];
        const int prev = (i == 0) ? -1 : seg_ids[i - 1];
        for (int sg = prev + 1; sg <= cur; sg++) g_starts[sg] = i;
        if (i == NTOT - 1)
            for (int sg = cur + 1; sg <= NSEG; sg++) g_starts[sg] = NTOT;
    } else {
        const int i = (bid - PREP_ST) * 256 + threadIdx.x;  // float4 index
        if (i >= NENT * H / 4) return;
        const float4 x = reinterpret_cast<const float4*>(ent)[i];
        const __half h0 = __float2half_rn(x.x);
        const __half h1 = __float2half_rn(x.y);
        const __half h2 = __float2half_rn(x.z);
        const __half h3 = __float2half_rn(x.w);
        __half2* ph = reinterpret_cast<__half2*>(g_Ehi) + 2 * (size_t)i;
        __half2* pl = reinterpret_cast<__half2*>(g_Elo) + 2 * (size_t)i;
        ph[0] = __halves2half2(h0, h1);
        ph[1] = __halves2half2(h2, h3);
        pl[0] = __floats2half2_rn(x.x - __half2float(h0),
                                  x.y - __half2float(h1));
        pl[1] = __floats2half2_rn(x.z - __half2float(h2),
                                  x.w - __half2float(h3));
    }
}

// ===========================================================================
// Kernel 1 (MERGED GEMMs, one launch, 884 blocks):
//  blocks [0, 256):    aq path  — A = [s|r] @ W[256:768] + b, 32x64 FFMA2 tiles
//  blocks [256, 884):  ew1 path — EW1 = ent @ W1 via HMMA fp16 2-product
//                      (A hi/lo residual split, B single fp16); fp16 output.
// ===========================================================================
#define AQ_BLOCKS  256              // 64 qBase x 4 nBase
#define EW1_BLOCKS 628              // 157 eBase x 4 nBase
#define MM_AHI 0
#define MM_ALO 16384
#define MM_BH  32768
#define MM_SMEM 40960

// ---- aq sub-kernel: QBM=32, QBN=64, BK=32, FFMA2, register prefetch ----
__device__ __forceinline__ void aq_path(char* smem, int bid,
                                        const int* __restrict__ s,
                                        const int* __restrict__ r,
                                        const float* __restrict__ ent,
                                        const float* __restrict__ rel,
                                        const float* __restrict__ W,
                                        const float* __restrict__ b) {
    float4* sA = reinterpret_cast<float4*>(smem);            // 32*17 = 544 f4
    float4* sW = reinterpret_cast<float4*>(smem + 8704);     // 512 f4
    int* sidx  = reinterpret_cast<int*>(smem + 8704 + 8192); // 32
    int* ridx  = sidx + 32;

    const int tid   = threadIdx.x;
    const int tm    = tid >> 4;            // 0..15 (2 rows each)
    const int tn    = tid & 15;            // 0..15 (4 cols)
    const int qBase = (bid & 63) * 32;
    const int nBase = (bid >> 6) * 64;

    if (tid < 32) { sidx[tid] = s[qBase + tid]; ridx[tid] = r[qBase + tid]; }
    __syncthreads();

    const int e0  = tid >> 3;              // 0..31 A row
    const int k4  = tid & 7;               // A f4-in-row
    const int swk = tid >> 4;              // W rows swk, swk+16
    const int swc = tid & 15;

    float2 acc[2][2];
#pragma unroll
    for (int e = 0; e < 2; e++) {
        acc[e][0] = make_float2(0.f, 0.f);
        acc[e][1] = make_float2(0.f, 0.f);
    }

    auto aSrc = [&](int kc, int e) -> const float* {
        return (kc < H) ? ent + (size_t)sidx[e] * H + kc
                        : rel + (size_t)ridx[e] * H + (kc - H);
    };

    float4 pa  = *reinterpret_cast<const float4*>(aSrc(0, e0) + k4 * 4);
    float4 pw0 = *(reinterpret_cast<const float4*>(
                       W + (size_t)(H + swk) * H + nBase) + swc);
    float4 pw1 = *(reinterpret_cast<const float4*>(
                       W + (size_t)(H + swk + 16) * H + nBase) + swc);

#pragma unroll 1
    for (int kc = 0; kc < 2 * H; kc += 32) {
        if (kc) __syncthreads();
        sA[e0 * 17 + k4 * 2 + 0] = make_float4(pa.x, pa.x, pa.y, pa.y);
        sA[e0 * 17 + k4 * 2 + 1] = make_float4(pa.z, pa.z, pa.w, pa.w);
        sW[swk * 16 + swc]        = pw0;
        sW[(swk + 16) * 16 + swc] = pw1;
        __syncthreads();

        if (kc + 32 < 2 * H) {
            const int kn = kc + 32;
            pa  = *reinterpret_cast<const float4*>(aSrc(kn, e0) + k4 * 4);
            pw0 = *(reinterpret_cast<const float4*>(
                        W + (size_t)(H + kn + swk) * H + nBase) + swc);
            pw1 = *(reinterpret_cast<const float4*>(
                        W + (size_t)(H + kn + swk + 16) * H + nBase) + swc);
        }

#pragma unroll
        for (int k2 = 0; k2 < 16; k2++) {
            const float4 w0 = sW[(2 * k2) * 16 + tn];
            const float4 w1 = sW[(2 * k2 + 1) * 16 + tn];
#pragma unroll
            for (int e = 0; e < 2; e++) {
                const float4 a = sA[(tm * 2 + e) * 17 + k2];
                acc[e][0] = ffma2(f2lo(a), f2lo(w0), acc[e][0]);
                acc[e][1] = ffma2(f2lo(a), f2hi(w0), acc[e][1]);
                acc[e][0] = ffma2(f2hi(a), f2lo(w1), acc[e][0]);
                acc[e][1] = ffma2(f2hi(a), f2hi(w1), acc[e][1]);
            }
        }
    }

    const float4 b4 = *reinterpret_cast<const float4*>(b + nBase + tn * 4);
#pragma unroll
    for (int e = 0; e < 2; e++) {
        float* row = g_A + (size_t)(qBase + tm * 2 + e) * H + nBase;
        *reinterpret_cast<float4*>(row + tn * 4) =
            make_float4(acc[e][0].x + b4.x, acc[e][0].y + b4.y,
                        acc[e][1].x + b4.z, acc[e][1].y + b4.w);
    }
}

// ---- ew1 sub-kernel: HMMA fp16 2-product (pre-split A, single B) ----
__device__ __forceinline__ void ew1_path(char* smem, int bid) {
    const uint32_t sb = smem_u32(smem);
    const int tid   = threadIdx.x;
    const int wid   = tid >> 5;
    const int lane  = tid & 31;
    const int wm    = wid & 3;
    const int wn    = wid >> 2;
    const int eBase = (bid % 157) * 128;
    const int nBase = (bid / 157) * 64;

    const int lmat = lane >> 3;
    const int lrow = lane & 7;

    float acc[2][4][4];
#pragma unroll
    for (int mt = 0; mt < 2; mt++)
#pragma unroll
        for (int nt = 0; nt < 4; nt++)
#pragma unroll
            for (int j = 0; j < 4; j++) acc[mt][nt][j] = 0.0f;

#pragma unroll 1
    for (int c = 0; c < 4; c++) {
        const int kc = c * 64;
        if (c) __syncthreads();

        // ---- stage A hi/lo: 128 rows x 64 fp16 = 1024 uint4 -> 4/thread ----
#pragma unroll
        for (int it = 0; it < 4; it++) {
            const int idx = tid + it * 256;        // 0..1023
            const int row = idx >> 3;
            const int seg = idx & 7;
            int er = eBase + row; if (er >= NENT) er = 0;
            const uint4 vh = *reinterpret_cast<const uint4*>(
                                 g_Ehi + (size_t)er * H + kc + seg * 8);
            const uint4 vl = *reinterpret_cast<const uint4*>(
                                 g_Elo + (size_t)er * H + kc + seg * 8);
            const uint32_t sw = sw128(row * 128 + seg * 16);
            *reinterpret_cast<uint4*>(smem + MM_AHI + sw) = vh;
            *reinterpret_cast<uint4*>(smem + MM_ALO + sw) = vl;
        }
        // ---- stage B: 64 n-rows x 64 fp16 = 512 uint4 -> 2/thread ----
#pragma unroll
        for (int it = 0; it < 2; it++) {
            const int idx = tid + it * 256;        // 0..511
            const int n   = idx >> 3;
            const int seg = idx & 7;
            const uint4 vh = *reinterpret_cast<const uint4*>(
                                 g_Wth + (nBase + n) * H + kc + seg * 8);
            const uint32_t sw = sw128(n * 128 + seg * 16);
            *reinterpret_cast<uint4*>(smem + MM_BH + sw) = vh;
        }
        __syncthreads();

#pragma unroll
        for (int kk = 0; kk < 4; kk++) {
            uint32_t ah[2][4], al[2][4];
#pragma unroll
            for (int mt = 0; mt < 2; mt++) {
                const int arow = wm * 32 + mt * 16 + ((lmat & 1) << 3) + lrow;
                const int akb  = (kk * 16 + ((lmat >> 1) << 3)) * 2;
                const uint32_t off = sw128(arow * 128 + akb);
                ldsm_x4(ah[mt], sb + MM_AHI + off);
                ldsm_x4(al[mt], sb + MM_ALO + off);
            }
            uint32_t bh[4][2];
#pragma unroll
            for (int np = 0; np < 2; np++) {
                const int brow = wn * 32 + np * 16 + ((lmat >> 1) << 3) + lrow;
                const int bkb  = (kk * 16 + ((lmat & 1) << 3)) * 2;
                const uint32_t off = sw128(brow * 128 + bkb);
                uint32_t th[4];
                ldsm_x4(th, sb + MM_BH + off);
                bh[2 * np + 0][0] = th[0]; bh[2 * np + 0][1] = th[1];
                bh[2 * np + 1][0] = th[2]; bh[2 * np + 1][1] = th[3];
            }
#pragma unroll
            for (int mt = 0; mt < 2; mt++)
#pragma unroll
                for (int nt = 0; nt < 4; nt++) {
                    mma_f16(acc[mt][nt], ah[mt], bh[nt]);
                    mma_f16(acc[mt][nt], al[mt], bh[nt]);
                }
        }
    }

    // epilogue: fp32 acc -> fp16 EW1
    const int gr = lane >> 2;
    const int gc = (lane & 3) * 2;
#pragma unroll
    for (int mt = 0; mt < 2; mt++) {
        const int m0 = eBase + wm * 32 + mt * 16 + gr;
        const int m1 = m0 + 8;
#pragma unroll
        for (int nt = 0; nt < 4; nt++) {
            const int n = nBase + wn * 32 + nt * 8 + gc;
            if (m0 < NENT)
                *reinterpret_cast<__half2*>(g_EW1h + (size_t)m0 * H + n) =
                    __floats2half2_rn(acc[mt][nt][0], acc[mt][nt][1]);
            if (m1 < NENT)
                *reinterpret_cast<__half2*>(g_EW1h + (size_t)m1 * H + n) =
                    __floats2half2_rn(acc[mt][nt][2], acc[mt][nt][3]);
        }
    }
}

__global__ void __launch_bounds__(256)
gemm_kernel(const float* __restrict__ ent,
            const int* __restrict__ s, const int* __restrict__ r,
            const float* __restrict__ rel,
            const float* __restrict__ W, const float* __restrict__ b) {
    extern __shared__ char smem[];
    const int bid = blockIdx.x;
    if (bid < AQ_BLOCKS) aq_path(smem, bid, s, r, ent, rel, W, b);
    else                 ew1_path(smem, bid - AQ_BLOCKS);
}

// ---------------------------------------------------------------------------
// Kernel 2 (FUSED, QUERY-PER-BLOCK): pass 1 reads fp16 EW1 (one LDG.128/lane
// per row); pass 2 gathers fp32 ent rows at float4 grain (R13-verified).
// ---------------------------------------------------------------------------
#define QCAP 512
__global__ void __launch_bounds__(256)
scoreagg_kernel(const int* __restrict__ s, const int* __restrict__ r,
                const int* __restrict__ nbr_ids,
                const float* __restrict__ ent,
                const float* __restrict__ rel,
                const float* __restrict__ v,
                float* __restrict__ out) {
    const int q    = blockIdx.x;
    const int tid  = threadIdx.x;
    const int w    = tid >> 5;
    const int lane = tid & 31;

    __shared__ int    sbnd[SEQL + 1];
    __shared__ float  wsm[QCAP];
    __shared__ int    nsm[QCAP];
    __shared__ float  sdsum[SEQL];

    if (tid <= SEQL) sbnd[tid] = g_starts[q * SEQL + tid];
    __syncthreads();
    const int qlo  = sbnd[0];
    const int qhi  = sbnd[SEQL];
    const int qcnt = qhi - qlo;

    // ---- pass 1: scores (2 neighbors per warp-iteration) ----
    if (qcnt > 0) {
        const float4* aq = reinterpret_cast<const float4*>(g_A + (size_t)q * H);
        const float4* vv = reinterpret_cast<const float4*>(v);
        const float4 a0 = aq[2 * lane], a1 = aq[2 * lane + 1];
        const float4 v0 = vv[2 * lane], v1 = vv[2 * lane + 1];

        for (int j0 = qlo + w; j0 < qhi; j0 += 16) {
            const int j1   = j0 + 8;
            const bool h1  = (j1 < qhi);
            const int n0   = nbr_ids[j0];
            const int n1   = nbr_ids[h1 ? j1 : j0];

            const uint4 eu0 = *reinterpret_cast<const uint4*>(
                                  g_EW1h + (size_t)n0 * H + lane * 8);
            const uint4 eu1 = *reinterpret_cast<const uint4*>(
                                  g_EW1h + (size_t)n1 * H + lane * 8);
            const __half2* e0 = reinterpret_cast<const __half2*>(&eu0);
            const __half2* e1 = reinterpret_cast<const __half2*>(&eu1);
            const float2 p0 = __half22float2(e0[0]);
            const float2 p1 = __half22float2(e0[1]);
            const float2 p2 = __half22float2(e0[2]);
            const float2 p3 = __half22float2(e0[3]);
            const float2 r0 = __half22float2(e1[0]);
            const float2 r1 = __half22float2(e1[1]);
            const float2 r2 = __half22float2(e1[2]);
            const float2 r3 = __half22float2(e1[3]);

            float sc0, sc1;
            sc0 = tanh_fast(p0.x + a0.x) * v0.x;
            sc1 = tanh_fast(r0.x + a0.x) * v0.x;
            sc0 = fmaf(tanh_fast(p0.y + a0.y), v0.y, sc0);
            sc1 = fmaf(tanh_fast(r0.y + a0.y), v0.y, sc1);
            sc0 = fmaf(tanh_fast(p1.x + a0.z), v0.z, sc0);
            sc1 = fmaf(tanh_fast(r1.x + a0.z), v0.z, sc1);
            sc0 = fmaf(tanh_fast(p1.y + a0.w), v0.w, sc0);
            sc1 = fmaf(tanh_fast(r1.y + a0.w), v0.w, sc1);
            sc0 = fmaf(tanh_fast(p2.x + a1.x), v1.x, sc0);
            sc1 = fmaf(tanh_fast(r2.x + a1.x), v1.x, sc1);
            sc0 = fmaf(tanh_fast(p2.y + a1.y), v1.y, sc0);
            sc1 = fmaf(tanh_fast(r2.y + a1.y), v1.y, sc1);
            sc0 = fmaf(tanh_fast(p3.x + a1.z), v1.z, sc0);
            sc1 = fmaf(tanh_fast(r3.x + a1.z), v1.z, sc1);
            sc0 = fmaf(tanh_fast(p3.y + a1.w), v1.w, sc0);
            sc1 = fmaf(tanh_fast(r3.y + a1.w), v1.w, sc1);
#pragma unroll
            for (int o = 16; o; o >>= 1) {
                sc0 += __shfl_xor_sync(0xffffffffu, sc0, o);
                sc1 += __shfl_xor_sync(0xffffffffu, sc1, o);
            }
            if (lane == 0) {
                const float e0v = __expf(sc0);
                const int k0 = j0 - qlo;
                if (k0 < QCAP) { wsm[k0] = e0v; nsm[k0] = n0; }
                else           g_scores[j0] = e0v;
                if (h1) {
                    const float e1v = __expf(sc1);
                    const int k1 = j1 - qlo;
                    if (k1 < QCAP) { wsm[k1] = e1v; nsm[k1] = n1; }
                    else           g_scores[j1] = e1v;
                }
            }
        }
    }
    __syncthreads();

    // ---- per-segment exp sums ----
    for (int t = w; t < SEQL; t += 8) {
        const int slo = sbnd[t]     - qlo;
        const int shi = sbnd[t + 1] - qlo;
        float d = 0.0f;
        for (int k = slo + lane; k < shi; k += 32)
            d += (k < QCAP) ? wsm[k] : g_scores[qlo + k];
#pragma unroll
        for (int o = 16; o; o >>= 1) d += __shfl_xor_sync(0xffffffffu, d, o);
        if (lane == 0) sdsum[t] = d;
    }

    // ---- pass 2: fp32 gather, float4 grain; group g owns {g, g+4, ...} ----
    const int g  = tid >> 6;               // 0..3
    const int h4 = tid & 63;               // float4 index within row
    const float4 s4 = *(reinterpret_cast<const float4*>(
                            ent + (size_t)s[q] * H) + h4);
    const float4 r4 = *(reinterpret_cast<const float4*>(
                            rel + (size_t)r[q] * H) + h4);
    __syncthreads();                        // wsm/nsm/sdsum ready

    float* qout = out + (size_t)q * SEQL * (3 * H);
#pragma unroll 1
    for (int t = g; t < SEQL; t += 4) {
        float* row = qout + (size_t)t * (3 * H);
        float4* rowA = reinterpret_cast<float4*>(row);
        float4* rowS = reinterpret_cast<float4*>(row + H);
        float4* rowR = reinterpret_cast<float4*>(row + 2 * H);
        const int slo = sbnd[t]     - qlo;
        const int shi = sbnd[t + 1] - qlo;

        if (slo >= shi) {
            const float4 z = make_float4(0.f, 0.f, 0.f, 0.f);
            rowA[h4] = z; rowS[h4] = z; rowR[h4] = z;
            continue;
        }
        const float inv = 1.0f / sdsum[t];
        const int c = min(shi, QCAP);

        float4 a0 = make_float4(0.f, 0.f, 0.f, 0.f);
        float4 a1 = make_float4(0.f, 0.f, 0.f, 0.f);
        int k = slo;
        for (; k + 1 < c; k += 2) {
            const float w0 = wsm[k], w1 = wsm[k + 1];
            const float4 e0 = *(reinterpret_cast<const float4*>(
                                    ent + (size_t)nsm[k] * H) + h4);
            const float4 e1 = *(reinterpret_cast<const float4*>(
                                    ent + (size_t)nsm[k + 1] * H) + h4);
            a0.x = fmaf(w0, e0.x, a0.x); a0.y = fmaf(w0, e0.y, a0.y);
            a0.z = fmaf(w0, e0.z, a0.z); a0.w = fmaf(w0, e0.w, a0.w);
            a1.x = fmaf(w1, e1.x, a1.x); a1.y = fmaf(w1, e1.y, a1.y);
            a1.z = fmaf(w1, e1.z, a1.z); a1.w = fmaf(w1, e1.w, a1.w);
        }
        for (; k < c; k++) {
            const float w0 = wsm[k];
            const float4 e0 = *(reinterpret_cast<const float4*>(
                                    ent + (size_t)nsm[k] * H) + h4);
            a0.x = fmaf(w0, e0.x, a0.x); a0.y = fmaf(w0, e0.y, a0.y);
            a0.z = fmaf(w0, e0.z, a0.z); a0.w = fmaf(w0, e0.w, a0.w);
        }
        for (; k < shi; k++) {              // spill path (rare)
            const float w0 = g_scores[qlo + k];
            const float4 e0 = *(reinterpret_cast<const float4*>(
                                    ent + (size_t)nbr_ids[qlo + k] * H) + h4);
            a0.x = fmaf(w0, e0.x, a0.x); a0.y = fmaf(w0, e0.y, a0.y);
            a0.z = fmaf(w0, e0.z, a0.z); a0.w = fmaf(w0, e0.w, a0.w);
        }

        rowA[h4] = make_float4((a0.x + a1.x) * inv, (a0.y + a1.y) * inv,
                               (a0.z + a1.z) * inv, (a0.w + a1.w) * inv);
        rowS[h4] = s4;
        rowR[h4] = r4;
    }
}

// ---------------------------------------------------------------------------
extern "C" void kernel_launch(void* const* d_in, const int* in_sizes, int n_in,
                              void* d_out, int out_size) {
    const int*   s    = (const int*)d_in[0];
    const int*   r    = (const int*)d_in[1];
    const int*   nbr  = (const int*)d_in[2];
    const int*   segi = (const int*)d_in[3];
    const float* ent  = (const float*)d_in[4];
    const float* rel  = (const float*)d_in[5];
    const float* W    = (const float*)d_in[6];
    const float* b    = (const float*)d_in[7];
    const float* v    = (const float*)d_in[8];
    float* out = (float*)d_out;

    cudaFuncSetAttribute(gemm_kernel,
                         cudaFuncAttributeMaxDynamicSharedMemorySize, MM_SMEM);

    prep_kernel<<<PREP_TOT, 256>>>(segi, W, ent);
    gemm_kernel<<<AQ_BLOCKS + EW1_BLOCKS, 256, MM_SMEM>>>(ent, s, r, rel, W, b);
    scoreagg_kernel<<<BQ, 256>>>(s, r, nbr, ent, rel, v, out);
}

// round 16
// speedup vs baseline: 1.0963x; 1.0494x over previous
#include <cuda_runtime.h>
#include <cuda_fp16.h>
#include <cstdint>

#define H     256
#define SEQL  10
#define BQ    2048
#define NTOT  327680
#define NSEG  (BQ * SEQL)  // 20480
#define NENT  20000

// ---------------- scratch (no cudaMalloc allowed) ----------------
__device__ __half g_EW1h[NENT * H];    // ent_embeds @ W1 in fp16 (10 MB)
__device__ __half g_Eh[NENT * H];      // ent in fp16 (10 MB, MMA A operand)
__device__ __half g_Wth[H * H];        // W1^T in fp16, [n][k]
__device__ float g_A[BQ * H];          // s@W2 + r@W3 + b   (2 MB)
__device__ float g_scores[NTOT];       // spill store for huge queries (rare)
__device__ int   g_starts[NSEG + 1];   // segment start offsets

// Packed fp32x2 FMA (Blackwell): two fp32 FMAs per instruction.
__device__ __forceinline__ float2 ffma2(float2 a, float2 b, float2 c) {
    float2 d;
    asm("fma.rn.f32x2 %0, %1, %2, %3;"
        : "=l"(reinterpret_cast<unsigned long long&>(d))
        : "l"(reinterpret_cast<const unsigned long long&>(a)),
          "l"(reinterpret_cast<const unsigned long long&>(b)),
          "l"(reinterpret_cast<const unsigned long long&>(c)));
    return d;
}

__device__ __forceinline__ float tanh_fast(float x) {
    float y;
    asm("tanh.approx.f32 %0, %1;" : "=f"(y) : "f"(x));
    return y;
}

__device__ __forceinline__ float2 f2lo(float4 v) { return make_float2(v.x, v.y); }
__device__ __forceinline__ float2 f2hi(float4 v) { return make_float2(v.z, v.w); }

__device__ __forceinline__ uint32_t smem_u32(const void* p) {
    uint32_t a;
    asm("{ .reg .u64 t; cvta.to.shared.u64 t, %1; cvt.u32.u64 %0, t; }"
        : "=r"(a) : "l"(p));
    return a;
}

__device__ __forceinline__ uint32_t sw128(uint32_t x) {
    return x ^ ((x >> 3) & 0x70);
}

__device__ __forceinline__ void ldsm_x4(uint32_t* r, uint32_t addr) {
    asm volatile("ldmatrix.sync.aligned.m8n8.x4.shared.b16 {%0,%1,%2,%3}, [%4];"
                 : "=r"(r[0]), "=r"(r[1]), "=r"(r[2]), "=r"(r[3]) : "r"(addr));
}

__device__ __forceinline__ void mma_f16(float* c, const uint32_t* a,
                                        const uint32_t* b) {
    asm volatile(
        "mma.sync.aligned.m16n8k16.row.col.f32.f16.f16.f32 "
        "{%0,%1,%2,%3}, {%4,%5,%6,%7}, {%8,%9}, {%0,%1,%2,%3};"
        : "+f"(c[0]), "+f"(c[1]), "+f"(c[2]), "+f"(c[3])
        : "r"(a[0]), "r"(a[1]), "r"(a[2]), "r"(a[3]), "r"(b[0]), "r"(b[1]));
}

// ===========================================================================
// Kernel 0 (FUSED prep):
//  blocks [0, 64):         transpose W1 -> g_Wth (fp16)
//  blocks [64, 1344):      segment start offsets from sorted seg_ids
//  blocks [1344, 6344):    convert ent -> g_Eh (fp16)
// ===========================================================================
#define PREP_W 64
#define PREP_ST (PREP_W + (NTOT + 255) / 256)               // 1344
#define PREP_TOT (PREP_ST + (NENT * H / 4 + 255) / 256)     // 6344

__global__ void __launch_bounds__(256)
prep_kernel(const int* __restrict__ seg_ids, const float* __restrict__ W,
            const float* __restrict__ ent) {
    const int bid = blockIdx.x;
    if (bid < PREP_W) {
        __shared__ float t[32][33];
        const int bx = bid & 7;
        const int by = bid >> 3;
        const int tx = threadIdx.x & 31;
        const int ty = threadIdx.x >> 5;
#pragma unroll
        for (int i = 0; i < 4; i++) {
            const int k = bx * 32 + ty + i * 8;
            const int n = by * 32 + tx;
            t[ty + i * 8][tx] = W[k * H + n];
        }
        __syncthreads();
#pragma unroll
        for (int i = 0; i < 4; i++) {
            const int n = by * 32 + ty + i * 8;
            const int k = bx * 32 + tx;
            g_Wth[n * H + k] = __float2half_rn(t[tx][ty + i * 8]);
        }
    } else if (bid < PREP_ST) {
        const int i = (bid - PREP_W) * 256 + threadIdx.x;
        if (i >= NTOT) return;
        const int cur  = seg_ids[i];
        const int prev = (i == 0) ? -1 : seg_ids[i - 1];
        for (int sg = prev + 1; sg <= cur; sg++) g_starts[sg] = i;
        if (i == NTOT - 1)
            for (int sg = cur + 1; sg <= NSEG; sg++) g_starts[sg] = NTOT;
    } else {
        const int i = (bid - PREP_ST) * 256 + threadIdx.x;  // float4 index
        if (i >= NENT * H / 4) return;
        const float4 x = reinterpret_cast<const float4*>(ent)[i];
        __half2* ph = reinterpret_cast<__half2*>(g_Eh) + 2 * (size_t)i;
        ph[0] = __floats2half2_rn(x.x, x.y);
        ph[1] = __floats2half2_rn(x.z, x.w);
    }
}

// ===========================================================================
// Kernel 1 (MERGED GEMMs, one launch, 884 blocks):
//  blocks [0, 256):    aq path  — A = [s|r] @ W[256:768] + b, 32x64 FFMA2 tiles
//  blocks [256, 884):  ew1 path — EW1 = ent @ W1 via single fp16 HMMA.
//                      FULL K=256 staged at once (96 KB smem, 4 panels of 64):
//                      ONE sync round per block, max LDG MLP, then 16
//                      uninterrupted k16 steps. fp16 output.
// ===========================================================================
#define AQ_BLOCKS  256              // 64 qBase x 4 nBase
#define EW1_BLOCKS 628              // 157 eBase x 4 nBase
#define MM_A   0                    // 4 panels x 16 KB = 64 KB
#define MM_B   65536                // 4 panels x 8 KB  = 32 KB
#define MM_SMEM 98304

// ---- aq sub-kernel: QBM=32, QBN=64, BK=32, FFMA2, register prefetch ----
__device__ __forceinline__ void aq_path(char* smem, int bid,
                                        const int* __restrict__ s,
                                        const int* __restrict__ r,
                                        const float* __restrict__ ent,
                                        const float* __restrict__ rel,
                                        const float* __restrict__ W,
                                        const float* __restrict__ b) {
    float4* sA = reinterpret_cast<float4*>(smem);            // 32*17 = 544 f4
    float4* sW = reinterpret_cast<float4*>(smem + 8704);     // 512 f4
    int* sidx  = reinterpret_cast<int*>(smem + 8704 + 8192); // 32
    int* ridx  = sidx + 32;

    const int tid   = threadIdx.x;
    const int tm    = tid >> 4;            // 0..15 (2 rows each)
    const int tn    = tid & 15;            // 0..15 (4 cols)
    const int qBase = (bid & 63) * 32;
    const int nBase = (bid >> 6) * 64;

    if (tid < 32) { sidx[tid] = s[qBase + tid]; ridx[tid] = r[qBase + tid]; }
    __syncthreads();

    const int e0  = tid >> 3;              // 0..31 A row
    const int k4  = tid & 7;               // A f4-in-row
    const int swk = tid >> 4;              // W rows swk, swk+16
    const int swc = tid & 15;

    float2 acc[2][2];
#pragma unroll
    for (int e = 0; e < 2; e++) {
        acc[e][0] = make_float2(0.f, 0.f);
        acc[e][1] = make_float2(0.f, 0.f);
    }

    auto aSrc = [&](int kc, int e) -> const float* {
        return (kc < H) ? ent + (size_t)sidx[e] * H + kc
                        : rel + (size_t)ridx[e] * H + (kc - H);
    };

    float4 pa  = *reinterpret_cast<const float4*>(aSrc(0, e0) + k4 * 4);
    float4 pw0 = *(reinterpret_cast<const float4*>(
                       W + (size_t)(H + swk) * H + nBase) + swc);
    float4 pw1 = *(reinterpret_cast<const float4*>(
                       W + (size_t)(H + swk + 16) * H + nBase) + swc);

#pragma unroll 1
    for (int kc = 0; kc < 2 * H; kc += 32) {
        if (kc) __syncthreads();
        sA[e0 * 17 + k4 * 2 + 0] = make_float4(pa.x, pa.x, pa.y, pa.y);
        sA[e0 * 17 + k4 * 2 + 1] = make_float4(pa.z, pa.z, pa.w, pa.w);
        sW[swk * 16 + swc]        = pw0;
        sW[(swk + 16) * 16 + swc] = pw1;
        __syncthreads();

        if (kc + 32 < 2 * H) {
            const int kn = kc + 32;
            pa  = *reinterpret_cast<const float4*>(aSrc(kn, e0) + k4 * 4);
            pw0 = *(reinterpret_cast<const float4*>(
                        W + (size_t)(H + kn + swk) * H + nBase) + swc);
            pw1 = *(reinterpret_cast<const float4*>(
                        W + (size_t)(H + kn + swk + 16) * H + nBase) + swc);
        }

#pragma unroll
        for (int k2 = 0; k2 < 16; k2++) {
            const float4 w0 = sW[(2 * k2) * 16 + tn];
            const float4 w1 = sW[(2 * k2 + 1) * 16 + tn];
#pragma unroll
            for (int e = 0; e < 2; e++) {
                const float4 a = sA[(tm * 2 + e) * 17 + k2];
                acc[e][0] = ffma2(f2lo(a), f2lo(w0), acc[e][0]);
                acc[e][1] = ffma2(f2lo(a), f2hi(w0), acc[e][1]);
                acc[e][0] = ffma2(f2hi(a), f2lo(w1), acc[e][0]);
                acc[e][1] = ffma2(f2hi(a), f2hi(w1), acc[e][1]);
            }
        }
    }

    const float4 b4 = *reinterpret_cast<const float4*>(b + nBase + tn * 4);
#pragma unroll
    for (int e = 0; e < 2; e++) {
        float* row = g_A + (size_t)(qBase + tm * 2 + e) * H + nBase;
        *reinterpret_cast<float4*>(row + tn * 4) =
            make_float4(acc[e][0].x + b4.x, acc[e][0].y + b4.y,
                        acc[e][1].x + b4.z, acc[e][1].y + b4.w);
    }
}

// ---- ew1 sub-kernel: single fp16 HMMA, full-K staging, one sync round ----
__device__ __forceinline__ void ew1_path(char* smem, int bid) {
    const uint32_t sb = smem_u32(smem);
    const int tid   = threadIdx.x;
    const int wid   = tid >> 5;
    const int lane  = tid & 31;
    const int wm    = wid & 3;
    const int wn    = wid >> 2;
    const int eBase = (bid % 157) * 128;
    const int nBase = (bid / 157) * 64;

    const int lmat = lane >> 3;
    const int lrow = lane & 7;

    // ---- stage A: 4 panels x (128 rows x 64 fp16) = 4096 uint4, 16/thread ----
    {
        const int row = tid >> 1;                    // 0..127
        const int sg0 = (tid & 1) * 4;               // 0 or 4
        int er = eBase + row; if (er >= NENT) er = 0;
        const __half* src = g_Eh + (size_t)er * H;
#pragma unroll
        for (int p = 0; p < 4; p++) {
#pragma unroll
            for (int j = 0; j < 4; j++) {
                const int seg = sg0 + j;
                const uint4 v = *reinterpret_cast<const uint4*>(
                                    src + p * 64 + seg * 8);
                *reinterpret_cast<uint4*>(
                    smem + MM_A + p * 16384 + sw128(row * 128 + seg * 16)) = v;
            }
        }
    }
    // ---- stage B: 4 panels x (64 rows x 64 fp16) = 2048 uint4, 8/thread ----
    {
        const int n   = tid >> 2;                    // 0..63
        const int sg0 = (tid & 3) * 2;               // 0,2,4,6
        const __half* src = g_Wth + (size_t)(nBase + n) * H;
#pragma unroll
        for (int p = 0; p < 4; p++) {
#pragma unroll
            for (int j = 0; j < 2; j++) {
                const int seg = sg0 + j;
                const uint4 v = *reinterpret_cast<const uint4*>(
                                    src + p * 64 + seg * 8);
                *reinterpret_cast<uint4*>(
                    smem + MM_B + p * 8192 + sw128(n * 128 + seg * 16)) = v;
            }
        }
    }
    __syncthreads();

    float acc[2][4][4];
#pragma unroll
    for (int mt = 0; mt < 2; mt++)
#pragma unroll
        for (int nt = 0; nt < 4; nt++)
#pragma unroll
            for (int j = 0; j < 4; j++) acc[mt][nt][j] = 0.0f;

#pragma unroll
    for (int kk = 0; kk < 16; kk++) {
        const int p    = kk >> 2;
        const int kkin = kk & 3;
        uint32_t ah[2][4];
#pragma unroll
        for (int mt = 0; mt < 2; mt++) {
            const int arow = wm * 32 + mt * 16 + ((lmat & 1) << 3) + lrow;
            const int akb  = (kkin * 16 + ((lmat >> 1) << 3)) * 2;
            ldsm_x4(ah[mt], sb + MM_A + p * 16384 + sw128(arow * 128 + akb));
        }
        uint32_t bh[4][2];
#pragma unroll
        for (int np = 0; np < 2; np++) {
            const int brow = wn * 32 + np * 16 + ((lmat >> 1) << 3) + lrow;
            const int bkb  = (kkin * 16 + ((lmat & 1) << 3)) * 2;
            uint32_t th[4];
            ldsm_x4(th, sb + MM_B + p * 8192 + sw128(brow * 128 + bkb));
            bh[2 * np + 0][0] = th[0]; bh[2 * np + 0][1] = th[1];
            bh[2 * np + 1][0] = th[2]; bh[2 * np + 1][1] = th[3];
        }
#pragma unroll
        for (int mt = 0; mt < 2; mt++)
#pragma unroll
            for (int nt = 0; nt < 4; nt++)
                mma_f16(acc[mt][nt], ah[mt], bh[nt]);
    }

    // epilogue: fp32 acc -> fp16 EW1
    const int gr = lane >> 2;
    const int gc = (lane & 3) * 2;
#pragma unroll
    for (int mt = 0; mt < 2; mt++) {
        const int m0 = eBase + wm * 32 + mt * 16 + gr;
        const int m1 = m0 + 8;
#pragma unroll
        for (int nt = 0; nt < 4; nt++) {
            const int n = nBase + wn * 32 + nt * 8 + gc;
            if (m0 < NENT)
                *reinterpret_cast<__half2*>(g_EW1h + (size_t)m0 * H + n) =
                    __floats2half2_rn(acc[mt][nt][0], acc[mt][nt][1]);
            if (m1 < NENT)
                *reinterpret_cast<__half2*>(g_EW1h + (size_t)m1 * H + n) =
                    __floats2half2_rn(acc[mt][nt][2], acc[mt][nt][3]);
        }
    }
}

__global__ void __launch_bounds__(256)
gemm_kernel(const float* __restrict__ ent,
            const int* __restrict__ s, const int* __restrict__ r,
            const float* __restrict__ rel,
            const float* __restrict__ W, const float* __restrict__ b) {
    extern __shared__ char smem[];
    const int bid = blockIdx.x;
    if (bid < AQ_BLOCKS) aq_path(smem, bid, s, r, ent, rel, W, b);
    else                 ew1_path(smem, bid - AQ_BLOCKS);
}

// ---------------------------------------------------------------------------
// Kernel 2 (FUSED, QUERY-PER-BLOCK): pass 1 reads fp16 EW1 (one LDG.128/lane
// per row); pass 2 gathers fp32 ent rows at float4 grain (R13-verified).
// ---------------------------------------------------------------------------
#define QCAP 512
__global__ void __launch_bounds__(256)
scoreagg_kernel(const int* __restrict__ s, const int* __restrict__ r,
                const int* __restrict__ nbr_ids,
                const float* __restrict__ ent,
                const float* __restrict__ rel,
                const float* __restrict__ v,
                float* __restrict__ out) {
    const int q    = blockIdx.x;
    const int tid  = threadIdx.x;
    const int w    = tid >> 5;
    const int lane = tid & 31;

    __shared__ int    sbnd[SEQL + 1];
    __shared__ float  wsm[QCAP];
    __shared__ int    nsm[QCAP];
    __shared__ float  sdsum[SEQL];

    if (tid <= SEQL) sbnd[tid] = g_starts[q * SEQL + tid];
    __syncthreads();
    const int qlo  = sbnd[0];
    const int qhi  = sbnd[SEQL];
    const int qcnt = qhi - qlo;

    // ---- pass 1: scores (2 neighbors per warp-iteration) ----
    if (qcnt > 0) {
        const float4* aq = reinterpret_cast<const float4*>(g_A + (size_t)q * H);
        const float4* vv = reinterpret_cast<const float4*>(v);
        const float4 a0 = aq[2 * lane], a1 = aq[2 * lane + 1];
        const float4 v0 = vv[2 * lane], v1 = vv[2 * lane + 1];

        for (int j0 = qlo + w; j0 < qhi; j0 += 16) {
            const int j1   = j0 + 8;
            const bool h1  = (j1 < qhi);
            const int n0   = nbr_ids[j0];
            const int n1   = nbr_ids[h1 ? j1 : j0];

            const uint4 eu0 = *reinterpret_cast<const uint4*>(
                                  g_EW1h + (size_t)n0 * H + lane * 8);
            const uint4 eu1 = *reinterpret_cast<const uint4*>(
                                  g_EW1h + (size_t)n1 * H + lane * 8);
            const __half2* e0 = reinterpret_cast<const __half2*>(&eu0);
            const __half2* e1 = reinterpret_cast<const __half2*>(&eu1);
            const float2 p0 = __half22float2(e0[0]);
            const float2 p1 = __half22float2(e0[1]);
            const float2 p2 = __half22float2(e0[2]);
            const float2 p3 = __half22float2(e0[3]);
            const float2 r0 = __half22float2(e1[0]);
            const float2 r1 = __half22float2(e1[1]);
            const float2 r2 = __half22float2(e1[2]);
            const float2 r3 = __half22float2(e1[3]);

            float sc0, sc1;
            sc0 = tanh_fast(p0.x + a0.x) * v0.x;
            sc1 = tanh_fast(r0.x + a0.x) * v0.x;
            sc0 = fmaf(tanh_fast(p0.y + a0.y), v0.y, sc0);
            sc1 = fmaf(tanh_fast(r0.y + a0.y), v0.y, sc1);
            sc0 = fmaf(tanh_fast(p1.x + a0.z), v0.z, sc0);
            sc1 = fmaf(tanh_fast(r1.x + a0.z), v0.z, sc1);
            sc0 = fmaf(tanh_fast(p1.y + a0.w), v0.w, sc0);
            sc1 = fmaf(tanh_fast(r1.y + a0.w), v0.w, sc1);
            sc0 = fmaf(tanh_fast(p2.x + a1.x), v1.x, sc0);
            sc1 = fmaf(tanh_fast(r2.x + a1.x), v1.x, sc1);
            sc0 = fmaf(tanh_fast(p2.y + a1.y), v1.y, sc0);
            sc1 = fmaf(tanh_fast(r2.y + a1.y), v1.y, sc1);
            sc0 = fmaf(tanh_fast(p3.x + a1.z), v1.z, sc0);
            sc1 = fmaf(tanh_fast(r3.x + a1.z), v1.z, sc1);
            sc0 = fmaf(tanh_fast(p3.y + a1.w), v1.w, sc0);
            sc1 = fmaf(tanh_fast(r3.y + a1.w), v1.w, sc1);
#pragma unroll
            for (int o = 16; o; o >>= 1) {
                sc0 += __shfl_xor_sync(0xffffffffu, sc0, o);
                sc1 += __shfl_xor_sync(0xffffffffu, sc1, o);
            }
            if (lane == 0) {
                const float e0v = __expf(sc0);
                const int k0 = j0 - qlo;
                if (k0 < QCAP) { wsm[k0] = e0v; nsm[k0] = n0; }
                else           g_scores[j0] = e0v;
                if (h1) {
                    const float e1v = __expf(sc1);
                    const int k1 = j1 - qlo;
                    if (k1 < QCAP) { wsm[k1] = e1v; nsm[k1] = n1; }
                    else           g_scores[j1] = e1v;
                }
            }
        }
    }
    __syncthreads();

    // ---- per-segment exp sums ----
    for (int t = w; t < SEQL; t += 8) {
        const int slo = sbnd[t]     - qlo;
        const int shi = sbnd[t + 1] - qlo;
        float d = 0.0f;
        for (int k = slo + lane; k < shi; k += 32)
            d += (k < QCAP) ? wsm[k] : g_scores[qlo + k];
#pragma unroll
        for (int o = 16; o; o >>= 1) d += __shfl_xor_sync(0xffffffffu, d, o);
        if (lane == 0) sdsum[t] = d;
    }

    // ---- pass 2: fp32 gather, float4 grain; group g owns {g, g+4, ...} ----
    const int g  = tid >> 6;               // 0..3
    const int h4 = tid & 63;               // float4 index within row
    const float4 s4 = *(reinterpret_cast<const float4*>(
                            ent + (size_t)s[q] * H) + h4);
    const float4 r4 = *(reinterpret_cast<const float4*>(
                            rel + (size_t)r[q] * H) + h4);
    __syncthreads();                        // wsm/nsm/sdsum ready

    float* qout = out + (size_t)q * SEQL * (3 * H);
#pragma unroll 1
    for (int t = g; t < SEQL; t += 4) {
        float* row = qout + (size_t)t * (3 * H);
        float4* rowA = reinterpret_cast<float4*>(row);
        float4* rowS = reinterpret_cast<float4*>(row + H);
        float4* rowR = reinterpret_cast<float4*>(row + 2 * H);
        const int slo = sbnd[t]     - qlo;
        const int shi = sbnd[t + 1] - qlo;

        if (slo >= shi) {
            const float4 z = make_float4(0.f, 0.f, 0.f, 0.f);
            rowA[h4] = z; rowS[h4] = z; rowR[h4] = z;
            continue;
        }
        const float inv = 1.0f / sdsum[t];
        const int c = min(shi, QCAP);

        float4 a0 = make_float4(0.f, 0.f, 0.f, 0.f);
        float4 a1 = make_float4(0.f, 0.f, 0.f, 0.f);
        int k = slo;
        for (; k + 1 < c; k += 2) {
            const float w0 = wsm[k], w1 = wsm[k + 1];
            const float4 e0 = *(reinterpret_cast<const float4*>(
                                    ent + (size_t)nsm[k] * H) + h4);
            const float4 e1 = *(reinterpret_cast<const float4*>(
                                    ent + (size_t)nsm[k + 1] * H) + h4);
            a0.x = fmaf(w0, e0.x, a0.x); a0.y = fmaf(w0, e0.y, a0.y);
            a0.z = fmaf(w0, e0.z, a0.z); a0.w = fmaf(w0, e0.w, a0.w);
            a1.x = fmaf(w1, e1.x, a1.x); a1.y = fmaf(w1, e1.y, a1.y);
            a1.z = fmaf(w1, e1.z, a1.z); a1.w = fmaf(w1, e1.w, a1.w);
        }
        for (; k < c; k++) {
            const float w0 = wsm[k];
            const float4 e0 = *(reinterpret_cast<const float4*>(
                                    ent + (size_t)nsm[k] * H) + h4);
            a0.x = fmaf(w0, e0.x, a0.x); a0.y = fmaf(w0, e0.y, a0.y);
            a0.z = fmaf(w0, e0.z, a0.z); a0.w = fmaf(w0, e0.w, a0.w);
        }
        for (; k < shi; k++) {              // spill path (rare)
            const float w0 = g_scores[qlo + k];
            const float4 e0 = *(reinterpret_cast<const float4*>(
                                    ent + (size_t)nbr_ids[qlo + k] * H) + h4);
            a0.x = fmaf(w0, e0.x, a0.x); a0.y = fmaf(w0, e0.y, a0.y);
            a0.z = fmaf(w0, e0.z, a0.z); a0.w = fmaf(w0, e0.w, a0.w);
        }

        rowA[h4] = make_float4((a0.x + a1.x) * inv, (a0.y + a1.y) * inv,
                               (a0.z + a1.z) * inv, (a0.w + a1.w) * inv);
        rowS[h4] = s4;
        rowR[h4] = r4;
    }
}

// ---------------------------------------------------------------------------
extern "C" void kernel_launch(void* const* d_in, const int* in_sizes, int n_in,
                              void* d_out, int out_size) {
    const int*   s    = (const int*)d_in[0];
    const int*   r    = (const int*)d_in[1];
    const int*   nbr  = (const int*)d_in[2];
    const int*   segi = (const int*)d_in[3];
    const float* ent  = (const float*)d_in[4];
    const float* rel  = (const float*)d_in[5];
    const float* W    = (const float*)d_in[6];
    const float* b    = (const float*)d_in[7];
    const float* v    = (const float*)d_in[8];
    float* out = (float*)d_out;

    cudaFuncSetAttribute(gemm_kernel,
                         cudaFuncAttributeMaxDynamicSharedMemorySize, MM_SMEM);

    prep_kernel<<<PREP_TOT, 256>>>(segi, W, ent);
    gemm_kernel<<<AQ_BLOCKS + EW1_BLOCKS, 256, MM_SMEM>>>(ent, s, r, rel, W, b);
    scoreagg_kernel<<<BQ, 256>>>(s, r, nbr, ent, rel, v, out);
}

// round 17
// speedup vs baseline: 1.3161x; 1.2005x over previous
#include <cuda_runtime.h>
#include <cuda_fp16.h>
#include <cstdint>

#define H     256
#define SEQL  10
#define BQ    2048
#define NTOT  327680
#define NSEG  (BQ * SEQL)  // 20480
#define NENT  20000
#define NREL  200

// ---------------- scratch (no cudaMalloc allowed) ----------------
__device__ __half g_EW1h[NENT * H];    // ent_embeds @ W1 in fp16 (10 MB)
__device__ __half g_Eh[NENT * H];      // ent in fp16 (MMA A operand)
__device__ __half g_Rh[NREL * H];      // rel in fp16 (MMA A operand)
__device__ __half g_Wth[H * H];        // W1^T fp16, [n][k], k<256
__device__ __half g_WtA[H * 2 * H];    // (W2|W3)^T fp16, [n][k], k<512
__device__ float g_A[BQ * H];          // s@W2 + r@W3 + b   (2 MB)
__device__ float g_scores[NTOT];       // spill store for huge queries (rare)
__device__ int   g_starts[NSEG + 1];   // segment start offsets

__device__ __forceinline__ float tanh_fast(float x) {
    float y;
    asm("tanh.approx.f32 %0, %1;" : "=f"(y) : "f"(x));
    return y;
}

__device__ __forceinline__ uint32_t smem_u32(const void* p) {
    uint32_t a;
    asm("{ .reg .u64 t; cvta.to.shared.u64 t, %1; cvt.u32.u64 %0, t; }"
        : "=r"(a) : "l"(p));
    return a;
}

__device__ __forceinline__ uint32_t sw128(uint32_t x) {
    return x ^ ((x >> 3) & 0x70);
}

__device__ __forceinline__ void ldsm_x4(uint32_t* r, uint32_t addr) {
    asm volatile("ldmatrix.sync.aligned.m8n8.x4.shared.b16 {%0,%1,%2,%3}, [%4];"
                 : "=r"(r[0]), "=r"(r[1]), "=r"(r[2]), "=r"(r[3]) : "r"(addr));
}

__device__ __forceinline__ void mma_f16(float* c, const uint32_t* a,
                                        const uint32_t* b) {
    asm volatile(
        "mma.sync.aligned.m16n8k16.row.col.f32.f16.f16.f32 "
        "{%0,%1,%2,%3}, {%4,%5,%6,%7}, {%8,%9}, {%0,%1,%2,%3};"
        : "+f"(c[0]), "+f"(c[1]), "+f"(c[2]), "+f"(c[3])
        : "r"(a[0]), "r"(a[1]), "r"(a[2]), "r"(a[3]), "r"(b[0]), "r"(b[1]));
}

// ===========================================================================
// Kernel 0 (FUSED prep):
//  blocks [0, 192):        transpose all 768 W rows -> g_Wth (k<256) and
//                          g_WtA (k 256..768, reindexed 0..512)
//  blocks [192, 1472):     segment start offsets from sorted seg_ids
//  blocks [1472, 6472):    convert ent -> g_Eh (fp16)
//  blocks [6472, 6522):    convert rel -> g_Rh (fp16)
// ===========================================================================
#define PREP_W  192
#define PREP_ST (PREP_W + (NTOT + 255) / 256)               // 1472
#define PREP_E  (PREP_ST + (NENT * H / 4 + 255) / 256)      // 6472
#define PREP_TOT (PREP_E + (NREL * H / 4 + 255) / 256)      // 6522

__global__ void __launch_bounds__(256)
prep_kernel(const int* __restrict__ seg_ids, const float* __restrict__ W,
            const float* __restrict__ ent, const float* __restrict__ rel) {
    const int bid = blockIdx.x;
    if (bid < PREP_W) {
        __shared__ float t[32][33];
        const int bx = bid % 24;             // k tile (0..23, covers 768)
        const int by = bid / 24;             // n tile (0..7)
        const int tx = threadIdx.x & 31;
        const int ty = threadIdx.x >> 5;
#pragma unroll
        for (int i = 0; i < 4; i++) {
            const int k = bx * 32 + ty + i * 8;
            const int n = by * 32 + tx;
            t[ty + i * 8][tx] = W[(size_t)k * H + n];
        }
        __syncthreads();
#pragma unroll
        for (int i = 0; i < 4; i++) {
            const int n = by * 32 + ty + i * 8;
            const int k = bx * 32 + tx;
            const __half h = __float2half_rn(t[tx][ty + i * 8]);
            if (k < H) g_Wth[n * H + k] = h;
            else       g_WtA[n * 2 * H + (k - H)] = h;
        }
    } else if (bid < PREP_ST) {
        const int i = (bid - PREP_W) * 256 + threadIdx.x;
        if (i >= NTOT) return;
        const int cur  = seg_ids[i];
        const int prev = (i == 0) ? -1 : seg_ids[i - 1];
        for (int sg = prev + 1; sg <= cur; sg++) g_starts[sg] = i;
        if (i == NTOT - 1)
            for (int sg = cur + 1; sg <= NSEG; sg++) g_starts[sg] = NTOT;
    } else if (bid < PREP_E) {
        const int i = (bid - PREP_ST) * 256 + threadIdx.x;  // float4 index
        if (i >= NENT * H / 4) return;
        const float4 x = reinterpret_cast<const float4*>(ent)[i];
        __half2* ph = reinterpret_cast<__half2*>(g_Eh) + 2 * (size_t)i;
        ph[0] = __floats2half2_rn(x.x, x.y);
        ph[1] = __floats2half2_rn(x.z, x.w);
    } else {
        const int i = (bid - PREP_E) * 256 + threadIdx.x;
        if (i >= NREL * H / 4) return;
        const float4 x = reinterpret_cast<const float4*>(rel)[i];
        __half2* ph = reinterpret_cast<__half2*>(g_Rh) + 2 * (size_t)i;
        ph[0] = __floats2half2_rn(x.x, x.y);
        ph[1] = __floats2half2_rn(x.z, x.w);
    }
}

// ===========================================================================
// Kernel 1 (UNIFIED HMMA GEMMs, one launch, 692 blocks):
//  blocks [0, 628):    ew1 — EW1 = ent @ W1 (1 staging round, fp16 out)
//  blocks [628, 692):  aq  — A = s_emb@W2 + r_emb@W3 + b (2 staging rounds
//                      over the same accumulators, fp32 out)
// Tile: M=128 rows x N=64 cols x K=256 per round, 8 warps (4m x 2n),
// full-K staging (A 64 KB + B 32 KB), SW128 smem, ldmatrix + m16n8k16 fp16.
// A rows come from an smem row-pointer table (gathered embeddings).
// ===========================================================================
#define EW1_BLOCKS 628              // 157 eBase x 4 nBase
#define AQ_BLOCKS  64               // 16 qBase x 4 nBase
#define MM_A    0                   // 4 panels x 16 KB = 64 KB
#define MM_B    65536               // 4 panels x 8 KB  = 32 KB
#define MM_PTR  98304               // 128 x 8 B row-pointer table
#define MM_SMEM 99328

struct MmaAcc { float a[2][4][4]; };

// Stage full K=256 (A via rowPtr, B via base/stride/offset) and accumulate.
__device__ __forceinline__ void hmma_round(char* smem,
                                           const __half* const* rowPtr,
                                           const __half* Bbase, int bstride,
                                           int bo, MmaAcc& acc) {
    const uint32_t sb = smem_u32(smem);
    const int tid  = threadIdx.x;
    const int wid  = tid >> 5;
    const int lane = tid & 31;
    const int wm   = wid & 3;
    const int wn   = wid >> 2;
    const int lmat = lane >> 3;
    const int lrow = lane & 7;

    // stage A: 4 panels x (128 rows x 64 fp16) = 4096 uint4, 16/thread
    {
        const int row = tid >> 1;
        const int sg0 = (tid & 1) * 4;
        const __half* src = rowPtr[row];
#pragma unroll
        for (int p = 0; p < 4; p++) {
#pragma unroll
            for (int j = 0; j < 4; j++) {
                const int seg = sg0 + j;
                const uint4 v = *reinterpret_cast<const uint4*>(
                                    src + p * 64 + seg * 8);
                *reinterpret_cast<uint4*>(
                    smem + MM_A + p * 16384 + sw128(row * 128 + seg * 16)) = v;
            }
        }
    }
    // stage B: 4 panels x (64 rows x 64 fp16) = 2048 uint4, 8/thread
    {
        const int n   = tid >> 2;
        const int sg0 = (tid & 3) * 2;
        const __half* src = Bbase + (size_t)n * bstride + bo;
#pragma unroll
        for (int p = 0; p < 4; p++) {
#pragma unroll
            for (int j = 0; j < 2; j++) {
                const int seg = sg0 + j;
                const uint4 v = *reinterpret_cast<const uint4*>(
                                    src + p * 64 + seg * 8);
                *reinterpret_cast<uint4*>(
                    smem + MM_B + p * 8192 + sw128(n * 128 + seg * 16)) = v;
            }
        }
    }
    __syncthreads();

#pragma unroll
    for (int kk = 0; kk < 16; kk++) {
        const int p    = kk >> 2;
        const int kkin = kk & 3;
        uint32_t ah[2][4];
#pragma unroll
        for (int mt = 0; mt < 2; mt++) {
            const int arow = wm * 32 + mt * 16 + ((lmat & 1) << 3) + lrow;
            const int akb  = (kkin * 16 + ((lmat >> 1) << 3)) * 2;
            ldsm_x4(ah[mt], sb + MM_A + p * 16384 + sw128(arow * 128 + akb));
        }
        uint32_t bh[4][2];
#pragma unroll
        for (int np = 0; np < 2; np++) {
            const int brow = wn * 32 + np * 16 + ((lmat >> 1) << 3) + lrow;
            const int bkb  = (kkin * 16 + ((lmat & 1) << 3)) * 2;
            uint32_t th[4];
            ldsm_x4(th, sb + MM_B + p * 8192 + sw128(brow * 128 + bkb));
            bh[2 * np + 0][0] = th[0]; bh[2 * np + 0][1] = th[1];
            bh[2 * np + 1][0] = th[2]; bh[2 * np + 1][1] = th[3];
        }
#pragma unroll
        for (int mt = 0; mt < 2; mt++)
#pragma unroll
            for (int nt = 0; nt < 4; nt++)
                mma_f16(acc.a[mt][nt], ah[mt], bh[nt]);
    }
}

__global__ void __launch_bounds__(256)
gemm_kernel(const int* __restrict__ s, const int* __restrict__ r,
            const float* __restrict__ b) {
    extern __shared__ char smem[];
    const __half** rowPtr = reinterpret_cast<const __half**>(smem + MM_PTR);
    const int bid  = blockIdx.x;
    const int tid  = threadIdx.x;
    const int wid  = tid >> 5;
    const int lane = tid & 31;
    const int wm   = wid & 3;
    const int wn   = wid >> 2;
    const int gr   = lane >> 2;
    const int gc   = (lane & 3) * 2;

    MmaAcc acc;
#pragma unroll
    for (int mt = 0; mt < 2; mt++)
#pragma unroll
        for (int nt = 0; nt < 4; nt++)
#pragma unroll
            for (int j = 0; j < 4; j++) acc.a[mt][nt][j] = 0.0f;

    if (bid < EW1_BLOCKS) {
        const int eBase = (bid % 157) * 128;
        const int nBase = (bid / 157) * 64;
        if (tid < 128) {
            int er = eBase + tid; if (er >= NENT) er = 0;
            rowPtr[tid] = g_Eh + (size_t)er * H;
        }
        __syncthreads();
        hmma_round(smem, rowPtr, g_Wth + (size_t)nBase * H, H, 0, acc);

        // epilogue: fp16 EW1
#pragma unroll
        for (int mt = 0; mt < 2; mt++) {
            const int m0 = eBase + wm * 32 + mt * 16 + gr;
            const int m1 = m0 + 8;
#pragma unroll
            for (int nt = 0; nt < 4; nt++) {
                const int n = nBase + wn * 32 + nt * 8 + gc;
                if (m0 < NENT)
                    *reinterpret_cast<__half2*>(g_EW1h + (size_t)m0 * H + n) =
                        __floats2half2_rn(acc.a[mt][nt][0], acc.a[mt][nt][1]);
                if (m1 < NENT)
                    *reinterpret_cast<__half2*>(g_EW1h + (size_t)m1 * H + n) =
                        __floats2half2_rn(acc.a[mt][nt][2], acc.a[mt][nt][3]);
            }
        }
    } else {
        const int ab    = bid - EW1_BLOCKS;
        const int qBase = (ab & 15) * 128;
        const int nBase = (ab >> 4) * 64;

        // round 1: A = s_emb, B = W2^T (k 0..255 of g_WtA)
        if (tid < 128)
            rowPtr[tid] = g_Eh + (size_t)s[qBase + tid] * H;
        __syncthreads();
        hmma_round(smem, rowPtr, g_WtA + (size_t)nBase * 2 * H, 2 * H, 0, acc);

        // round 2: A = r_emb, B = W3^T (k 256..511 of g_WtA)
        __syncthreads();
        if (tid < 128)
            rowPtr[tid] = g_Rh + (size_t)r[qBase + tid] * H;
        __syncthreads();
        hmma_round(smem, rowPtr, g_WtA + (size_t)nBase * 2 * H, 2 * H, H, acc);

        // epilogue: + bias, fp32 g_A
#pragma unroll
        for (int mt = 0; mt < 2; mt++) {
            const int m0 = qBase + wm * 32 + mt * 16 + gr;
            const int m1 = m0 + 8;
#pragma unroll
            for (int nt = 0; nt < 4; nt++) {
                const int n = nBase + wn * 32 + nt * 8 + gc;
                const float2 bb = *reinterpret_cast<const float2*>(b + n);
                *reinterpret_cast<float2*>(g_A + (size_t)m0 * H + n) =
                    make_float2(acc.a[mt][nt][0] + bb.x, acc.a[mt][nt][1] + bb.y);
                *reinterpret_cast<float2*>(g_A + (size_t)m1 * H + n) =
                    make_float2(acc.a[mt][nt][2] + bb.x, acc.a[mt][nt][3] + bb.y);
            }
        }
    }
}

// ---------------------------------------------------------------------------
// Kernel 2 (FUSED, QUERY-PER-BLOCK): pass 1 reads fp16 EW1 (one LDG.128/lane
// per row); pass 2 gathers fp32 ent rows at float4 grain.  (R16-verbatim)
// ---------------------------------------------------------------------------
#define QCAP 512
__global__ void __launch_bounds__(256)
scoreagg_kernel(const int* __restrict__ s, const int* __restrict__ r,
                const int* __restrict__ nbr_ids,
                const float* __restrict__ ent,
                const float* __restrict__ rel,
                const float* __restrict__ v,
                float* __restrict__ out) {
    const int q    = blockIdx.x;
    const int tid  = threadIdx.x;
    const int w    = tid >> 5;
    const int lane = tid & 31;

    __shared__ int    sbnd[SEQL + 1];
    __shared__ float  wsm[QCAP];
    __shared__ int    nsm[QCAP];
    __shared__ float  sdsum[SEQL];

    if (tid <= SEQL) sbnd[tid] = g_starts[q * SEQL + tid];
    __syncthreads();
    const int qlo  = sbnd[0];
    const int qhi  = sbnd[SEQL];
    const int qcnt = qhi - qlo;

    if (qcnt > 0) {
        const float4* aq = reinterpret_cast<const float4*>(g_A + (size_t)q * H);
        const float4* vv = reinterpret_cast<const float4*>(v);
        const float4 a0 = aq[2 * lane], a1 = aq[2 * lane + 1];
        const float4 v0 = vv[2 * lane], v1 = vv[2 * lane + 1];

        for (int j0 = qlo + w; j0 < qhi; j0 += 16) {
            const int j1   = j0 + 8;
            const bool h1  = (j1 < qhi);
            const int n0   = nbr_ids[j0];
            const int n1   = nbr_ids[h1 ? j1 : j0];

            const uint4 eu0 = *reinterpret_cast<const uint4*>(
                                  g_EW1h + (size_t)n0 * H + lane * 8);
            const uint4 eu1 = *reinterpret_cast<const uint4*>(
                                  g_EW1h + (size_t)n1 * H + lane * 8);
            const __half2* e0 = reinterpret_cast<const __half2*>(&eu0);
            const __half2* e1 = reinterpret_cast<const __half2*>(&eu1);
            const float2 p0 = __half22float2(e0[0]);
            const float2 p1 = __half22float2(e0[1]);
            const float2 p2 = __half22float2(e0[2]);
            const float2 p3 = __half22float2(e0[3]);
            const float2 r0 = __half22float2(e1[0]);
            const float2 r1 = __half22float2(e1[1]);
            const float2 r2 = __half22float2(e1[2]);
            const float2 r3 = __half22float2(e1[3]);

            float sc0, sc1;
            sc0 = tanh_fast(p0.x + a0.x) * v0.x;
            sc1 = tanh_fast(r0.x + a0.x) * v0.x;
            sc0 = fmaf(tanh_fast(p0.y + a0.y), v0.y, sc0);
            sc1 = fmaf(tanh_fast(r0.y + a0.y), v0.y, sc1);
            sc0 = fmaf(tanh_fast(p1.x + a0.z), v0.z, sc0);
            sc1 = fmaf(tanh_fast(r1.x + a0.z), v0.z, sc1);
            sc0 = fmaf(tanh_fast(p1.y + a0.w), v0.w, sc0);
            sc1 = fmaf(tanh_fast(r1.y + a0.w), v0.w, sc1);
            sc0 = fmaf(tanh_fast(p2.x + a1.x), v1.x, sc0);
            sc1 = fmaf(tanh_fast(r2.x + a1.x), v1.x, sc1);
            sc0 = fmaf(tanh_fast(p2.y + a1.y), v1.y, sc0);
            sc1 = fmaf(tanh_fast(r2.y + a1.y), v1.y, sc1);
            sc0 = fmaf(tanh_fast(p3.x + a1.z), v1.z, sc0);
            sc1 = fmaf(tanh_fast(r3.x + a1.z), v1.z, sc1);
            sc0 = fmaf(tanh_fast(p3.y + a1.w), v1.w, sc0);
            sc1 = fmaf(tanh_fast(r3.y + a1.w), v1.w, sc1);
#pragma unroll
            for (int o = 16; o; o >>= 1) {
                sc0 += __shfl_xor_sync(0xffffffffu, sc0, o);
                sc1 += __shfl_xor_sync(0xffffffffu, sc1, o);
            }
            if (lane == 0) {
                const float e0v = __expf(sc0);
                const int k0 = j0 - qlo;
                if (k0 < QCAP) { wsm[k0] = e0v; nsm[k0] = n0; }
                else           g_scores[j0] = e0v;
                if (h1) {
                    const float e1v = __expf(sc1);
                    const int k1 = j1 - qlo;
                    if (k1 < QCAP) { wsm[k1] = e1v; nsm[k1] = n1; }
                    else           g_scores[j1] = e1v;
                }
            }
        }
    }
    __syncthreads();

    for (int t = w; t < SEQL; t += 8) {
        const int slo = sbnd[t]     - qlo;
        const int shi = sbnd[t + 1] - qlo;
        float d = 0.0f;
        for (int k = slo + lane; k < shi; k += 32)
            d += (k < QCAP) ? wsm[k] : g_scores[qlo + k];
#pragma unroll
        for (int o = 16; o; o >>= 1) d += __shfl_xor_sync(0xffffffffu, d, o);
        if (lane == 0) sdsum[t] = d;
    }

    const int g  = tid >> 6;               // 0..3
    const int h4 = tid & 63;               // float4 index within row
    const float4 s4 = *(reinterpret_cast<const float4*>(
                            ent + (size_t)s[q] * H) + h4);
    const float4 r4 = *(reinterpret_cast<const float4*>(
                            rel + (size_t)r[q] * H) + h4);
    __syncthreads();

    float* qout = out + (size_t)q * SEQL * (3 * H);
#pragma unroll 1
    for (int t = g; t < SEQL; t += 4) {
        float* row = qout + (size_t)t * (3 * H);
        float4* rowA = reinterpret_cast<float4*>(row);
        float4* rowS = reinterpret_cast<float4*>(row + H);
        float4* rowR = reinterpret_cast<float4*>(row + 2 * H);
        const int slo = sbnd[t]     - qlo;
        const int shi = sbnd[t + 1] - qlo;

        if (slo >= shi) {
            const float4 z = make_float4(0.f, 0.f, 0.f, 0.f);
            rowA[h4] = z; rowS[h4] = z; rowR[h4] = z;
            continue;
        }
        const float inv = 1.0f / sdsum[t];
        const int c = min(shi, QCAP);

        float4 a0 = make_float4(0.f, 0.f, 0.f, 0.f);
        float4 a1 = make_float4(0.f, 0.f, 0.f, 0.f);
        int k = slo;
        for (; k + 1 < c; k += 2) {
            const float w0 = wsm[k], w1 = wsm[k + 1];
            const float4 e0 = *(reinterpret_cast<const float4*>(
                                    ent + (size_t)nsm[k] * H) + h4);
            const float4 e1 = *(reinterpret_cast<const float4*>(
                                    ent + (size_t)nsm[k + 1] * H) + h4);
            a0.x = fmaf(w0, e0.x, a0.x); a0.y = fmaf(w0, e0.y, a0.y);
            a0.z = fmaf(w0, e0.z, a0.z); a0.w = fmaf(w0, e0.w, a0.w);
            a1.x = fmaf(w1, e1.x, a1.x); a1.y = fmaf(w1, e1.y, a1.y);
            a1.z = fmaf(w1, e1.z, a1.z); a1.w = fmaf(w1, e1.w, a1.w);
        }
        for (; k < c; k++) {
            const float w0 = wsm[k];
            const float4 e0 = *(reinterpret_cast<const float4*>(
                                    ent + (size_t)nsm[k] * H) + h4);
            a0.x = fmaf(w0, e0.x, a0.x); a0.y = fmaf(w0, e0.y, a0.y);
            a0.z = fmaf(w0, e0.z, a0.z); a0.w = fmaf(w0, e0.w, a0.w);
        }
        for (; k < shi; k++) {
            const float w0 = g_scores[qlo + k];
            const float4 e0 = *(reinterpret_cast<const float4*>(
                                    ent + (size_t)nbr_ids[qlo + k] * H) + h4);
            a0.x = fmaf(w0, e0.x, a0.x); a0.y = fmaf(w0, e0.y, a0.y);
            a0.z = fmaf(w0, e0.z, a0.z); a0.w = fmaf(w0, e0.w, a0.w);
        }

        rowA[h4] = make_float4((a0.x + a1.x) * inv, (a0.y + a1.y) * inv,
                               (a0.z + a1.z) * inv, (a0.w + a1.w) * inv);
        rowS[h4] = s4;
        rowR[h4] = r4;
    }
}

// ---------------------------------------------------------------------------
extern "C" void kernel_launch(void* const* d_in, const int* in_sizes, int n_in,
                              void* d_out, int out_size) {
    const int*   s    = (const int*)d_in[0];
    const int*   r    = (const int*)d_in[1];
    const int*   nbr  = (const int*)d_in[2];
    const int*   segi = (const int*)d_in[3];
    const float* ent  = (const float*)d_in[4];
    const float* rel  = (const float*)d_in[5];
    const float* W    = (const float*)d_in[6];
    const float* b    = (const float*)d_in[7];
    const float* v    = (const float*)d_in[8];
    float* out = (float*)d_out;

    cudaFuncSetAttribute(gemm_kernel,
                         cudaFuncAttributeMaxDynamicSharedMemorySize, MM_SMEM);

    prep_kernel<<<PREP_TOT, 256>>>(segi, W, ent, rel);
    gemm_kernel<<<EW1_BLOCKS + AQ_BLOCKS, 256, MM_SMEM>>>(s, r, b);
    scoreagg_kernel<<<BQ, 256>>>(s, r, nbr, ent, rel, v, out);
}